// round 12
// baseline (speedup 1.0000x reference)
#include <cuda_runtime.h>
#include <cuda_fp16.h>
#include <math.h>
#include <cstdint>

#define B_   8
#define T_   12
#define N_   307
#define D_   512
#define H_   8
#define HD_  64
#define M_TOT (B_*T_*N_)   // 29472
#define MP   320           // padded mask row pitch

// ---------------- device scratch (allocation-free rule) ----------------
__device__ float g_mask[N_*MP];            // premultiplied by 0.125*log2(e)
__device__ __half g_inq[M_TOT*D_];         // fp16 copies of inputs
__device__ __half g_ink[M_TOT*D_];
__device__ __half g_inv[M_TOT*D_];
__device__ __half g_qh[M_TOT*D_];          // projected q/k/v
__device__ __half g_kh[M_TOT*D_];
__device__ __half g_vh[M_TOT*D_];
__device__ __half g_oh[M_TOT*D_];          // attention output
__device__ __half g_wt[4*D_*D_];           // transposed fp16 weights [N][K]

__device__ __forceinline__ uint32_t pack_f16x2(float lo, float hi) {
    uint32_t r;
    asm("cvt.rn.f16x2.f32 %0, %1, %2;" : "=r"(r) : "f"(hi), "f"(lo));
    return r;
}
__device__ __forceinline__ float ex2f(float x) {
    float r;
    asm("ex2.approx.f32 %0, %1;" : "=f"(r) : "f"(x));
    return r;
}

// ---------------- fp32 -> fp16 bulk convert (8 elems/thread) -----------
__global__ void cvt_f16_kernel(const float* __restrict__ s0, const float* __restrict__ s1,
                               const float* __restrict__ s2,
                               __half* __restrict__ d0, __half* __restrict__ d1,
                               __half* __restrict__ d2)
{
    int z = blockIdx.y;
    const float* s = (z == 0) ? s0 : (z == 1) ? s1 : s2;
    __half* d      = (z == 0) ? d0 : (z == 1) ? d1 : d2;
    int i = blockIdx.x * 256 + threadIdx.x;
    const int n8 = M_TOT * D_ / 8;
    if (i < n8) {
        float4 a = ((const float4*)s)[2 * i];
        float4 b = ((const float4*)s)[2 * i + 1];
        uint4 o;
        o.x = pack_f16x2(a.x, a.y); o.y = pack_f16x2(a.z, a.w);
        o.z = pack_f16x2(b.x, b.y); o.w = pack_f16x2(b.z, b.w);
        ((uint4*)d)[i] = o;
    }
}

// ---------------- mask = row-softmax * (0.125*log2e), padded pitch -----
__global__ void mask_softmax_kernel(const float* __restrict__ sem,
                                    float* __restrict__ mask)
{
    int row = blockIdx.x;
    int tid = threadIdx.x;
    __shared__ float red[256];
    const float* x = sem + (size_t)row * N_;
    float v0 = (tid       < N_) ? x[tid]       : -INFINITY;
    float v1 = (tid + 256 < N_) ? x[tid + 256] : -INFINITY;
    red[tid] = fmaxf(v0, v1);
    __syncthreads();
    for (int s = 128; s > 0; s >>= 1) {
        if (tid < s) red[tid] = fmaxf(red[tid], red[tid + s]);
        __syncthreads();
    }
    float rowmax = red[0];
    __syncthreads();
    float e0 = (tid       < N_) ? __expf(v0 - rowmax) : 0.f;
    float e1 = (tid + 256 < N_) ? __expf(v1 - rowmax) : 0.f;
    red[tid] = e0 + e1;
    __syncthreads();
    for (int s = 128; s > 0; s >>= 1) {
        if (tid < s) red[tid] += red[tid + s];
        __syncthreads();
    }
    // fold softmax-normalize, attention scale (0.125) and log2(e) into the mask
    float inv = 0.180336880f / red[0];   // 0.125 * 1.44269504 / sum
    if (tid       < N_) mask[(size_t)row * MP + tid]       = e0 * inv;
    if (tid + 256 < N_) mask[(size_t)row * MP + tid + 256] = e1 * inv;
    if (tid == 0)
        for (int c = N_; c < MP; c++) mask[(size_t)row * MP + c] = 0.f;
}

// ---------------- W -> W^T (fp16), 4 matrices ----------------
__global__ void transpose_w_kernel(const float* __restrict__ w0,
                                   const float* __restrict__ w1,
                                   const float* __restrict__ w2,
                                   const float* __restrict__ w3,
                                   __half* __restrict__ wt)
{
    __shared__ float t[32][33];
    int z  = blockIdx.z;
    const float* src = (z == 0) ? w0 : (z == 1) ? w1 : (z == 2) ? w2 : w3;
    __half* dst = wt + (size_t)z * D_ * D_;
    int tx = threadIdx.x, ty = threadIdx.y;
    int bx = blockIdx.x * 32, by = blockIdx.y * 32;
    #pragma unroll
    for (int i = 0; i < 32; i += 8)
        t[ty + i][tx] = src[(size_t)(by + ty + i) * D_ + bx + tx];
    __syncthreads();
    #pragma unroll
    for (int i = 0; i < 32; i += 8)
        dst[(size_t)(bx + ty + i) * D_ + by + tx] = __float2half(t[tx][ty + i]);
}

// ---------------- fp16 GEMM, all-cp.async, 3-stage pipeline ------------
// tiles: 128x128x64, 256 thr = 8 warps (2m x 4n). A/W fp16 pitch 72.
#define GP 72
#define GTILE  (128 * GP)               // 9216 halves per tile
#define GSTAGE (2 * GTILE)              // A + W per stage
#define GEMM_SMEM (3 * GSTAGE * 2)      // 110592 B

__global__ __launch_bounds__(256, 2)
void gemm_bias_f16_kernel(const __half* __restrict__ A0, const __half* __restrict__ A1,
                          const __half* __restrict__ A2, const __half* __restrict__ WtB,
                          const float* __restrict__ b0p, const float* __restrict__ b1p,
                          const float* __restrict__ b2p,
                          void* __restrict__ C0, void* __restrict__ C1,
                          void* __restrict__ C2, int M, int f16_out)
{
    extern __shared__ __half gsh[];
    int z = blockIdx.z;
    const __half* A    = (z == 0) ? A0 : (z == 1) ? A1 : A2;
    const __half* Wt   = WtB + (size_t)z * D_ * D_;
    const float* bias  = (z == 0) ? b0p : (z == 1) ? b1p : b2p;
    void* Cv           = (z == 0) ? C0 : (z == 1) ? C1 : C2;

    int tid  = threadIdx.x;
    int lane = tid & 31;
    int wid  = tid >> 5;
    int warp_m = wid & 1;
    int warp_n = wid >> 1;
    int m0 = blockIdx.y * 128;
    int n0 = blockIdx.x * 128;

    float acc[4][4][4];
    #pragma unroll
    for (int mi = 0; mi < 4; mi++)
        #pragma unroll
        for (int ni = 0; ni < 4; ni++)
            #pragma unroll
            for (int r = 0; r < 4; r++) acc[mi][ni][r] = 0.f;

    // one stage = A slab (128x64) + W slab (128x64), both fp16 cp.async
    auto cpa = [&](int st, int k0) {
        __half* Ab = gsh + st * GSTAGE;
        __half* Wb = Ab + GTILE;
        #pragma unroll
        for (int r = 0; r < 4; r++) {
            int e   = tid + r * 256;       // 0..1023
            int row = e >> 3;              // 0..127
            int seg = e & 7;
            int gm = m0 + row;
            const __half* asrc = A + (size_t)(gm < M ? gm : 0) * D_ + k0 + seg * 8;
            int sz = (gm < M) ? 16 : 0;
            uint32_t ad = (uint32_t)__cvta_generic_to_shared(Ab + row * GP + seg * 8);
            asm volatile("cp.async.ca.shared.global [%0], [%1], 16, %2;"
                         :: "r"(ad), "l"(asrc), "r"(sz));
            const __half* wsrc = Wt + (size_t)(n0 + row) * D_ + k0 + seg * 8;
            uint32_t wd = (uint32_t)__cvta_generic_to_shared(Wb + row * GP + seg * 8);
            asm volatile("cp.async.ca.shared.global [%0], [%1], 16;"
                         :: "r"(wd), "l"(wsrc));
        }
        asm volatile("cp.async.commit_group;");
    };

    cpa(0, 0);
    cpa(1, 64);

    int arow_sub = lane & 15;
    int acol8    = (lane >> 4) * 8;
    int brow_sub = (lane & 7) + ((lane >> 3) & 1) * 8;
    int bcol8    = (lane >> 4) * 8;

    #pragma unroll
    for (int s = 0; s < 8; s++) {
        if (s < 7) asm volatile("cp.async.wait_group 1;" ::: "memory");
        else       asm volatile("cp.async.wait_group 0;" ::: "memory");
        __syncthreads();
        if (s + 2 < 8) cpa((s + 2) % 3, (s + 2) * 64);

        __half* Ab = gsh + (s % 3) * GSTAGE;
        __half* Wb = Ab + GTILE;
        #pragma unroll
        for (int kk = 0; kk < 4; kk++) {
            uint32_t a[4][4];
            #pragma unroll
            for (int mi = 0; mi < 4; mi++) {
                uint32_t sa = (uint32_t)__cvta_generic_to_shared(
                    Ab + (warp_m * 64 + mi * 16 + arow_sub) * GP + kk * 16 + acol8);
                asm volatile(
                    "ldmatrix.sync.aligned.m8n8.x4.shared.b16 {%0,%1,%2,%3}, [%4];"
                    : "=r"(a[mi][0]), "=r"(a[mi][1]), "=r"(a[mi][2]), "=r"(a[mi][3])
                    : "r"(sa));
            }
            uint32_t bfr[2][4];
            #pragma unroll
            for (int t = 0; t < 2; t++) {
                uint32_t sbb = (uint32_t)__cvta_generic_to_shared(
                    Wb + (warp_n * 32 + t * 16 + brow_sub) * GP + kk * 16 + bcol8);
                asm volatile(
                    "ldmatrix.sync.aligned.m8n8.x4.shared.b16 {%0,%1,%2,%3}, [%4];"
                    : "=r"(bfr[t][0]), "=r"(bfr[t][1]), "=r"(bfr[t][2]), "=r"(bfr[t][3])
                    : "r"(sbb));
            }
            #pragma unroll
            for (int ni = 0; ni < 4; ni++) {
                uint32_t b0 = bfr[ni >> 1][ni & 1];
                uint32_t b1 = bfr[ni >> 1][(ni & 1) + 2];
                #pragma unroll
                for (int mi = 0; mi < 4; mi++) {
                    asm volatile(
                        "mma.sync.aligned.m16n8k16.row.col.f32.f16.f16.f32 "
                        "{%0,%1,%2,%3}, {%4,%5,%6,%7}, {%8,%9}, {%0,%1,%2,%3};"
                        : "+f"(acc[mi][ni][0]), "+f"(acc[mi][ni][1]),
                          "+f"(acc[mi][ni][2]), "+f"(acc[mi][ni][3])
                        : "r"(a[mi][0]), "r"(a[mi][1]), "r"(a[mi][2]), "r"(a[mi][3]),
                          "r"(b0), "r"(b1));
                }
            }
        }
    }

    int crow = m0 + warp_m * 64 + (lane >> 2);
    int ccol0 = n0 + warp_n * 32 + 2 * (lane & 3);
    #pragma unroll
    for (int mi = 0; mi < 4; mi++) {
        int r0 = crow + mi * 16;
        #pragma unroll
        for (int ni = 0; ni < 4; ni++) {
            int cc = ccol0 + ni * 8;
            float bb0 = bias[cc], bb1 = bias[cc + 1];
            if (f16_out) {
                __half* C = (__half*)Cv;
                if (r0 < M)
                    *(uint32_t*)(C + (size_t)r0 * D_ + cc) =
                        pack_f16x2(acc[mi][ni][0] + bb0, acc[mi][ni][1] + bb1);
                if (r0 + 8 < M)
                    *(uint32_t*)(C + (size_t)(r0 + 8) * D_ + cc) =
                        pack_f16x2(acc[mi][ni][2] + bb0, acc[mi][ni][3] + bb1);
            } else {
                float* C = (float*)Cv;
                if (r0 < M) {
                    float2 o = make_float2(acc[mi][ni][0] + bb0, acc[mi][ni][1] + bb1);
                    *(float2*)(C + (size_t)r0 * D_ + cc) = o;
                }
                if (r0 + 8 < M) {
                    float2 o = make_float2(acc[mi][ni][2] + bb0, acc[mi][ni][3] + bb1);
                    *(float2*)(C + (size_t)(r0 + 8) * D_ + cc) = o;
                }
            }
        }
    }
}

// ---------------- fp16 flash attention (m16n8k16), fp16 output ---------
#define PB 72
#define ATTN_SMEM ((2*128*PB + 4*64*PB) * 2)   // 73728 B

__global__ __launch_bounds__(256, 2)
void attn_mma_kernel(const __half* __restrict__ q,
                     const __half* __restrict__ k,
                     const __half* __restrict__ v,
                     const float* __restrict__ mask,
                     __half* __restrict__ out)
{
    extern __shared__ char smc[];
    uint32_t sb = (uint32_t)__cvta_generic_to_shared(smc);
    const uint32_t sQ = sb;
    const uint32_t sP = sb + 128 * PB * 2;
    const uint32_t sK0 = sb + 2 * 128 * PB * 2;
    const uint32_t sV0 = sK0 + 2 * 64 * PB * 2;

    int tid  = threadIdx.x;
    int lane = tid & 31;
    int wid  = tid >> 5;
    int bth  = blockIdx.y;
    int bt   = bth / H_;
    int h    = bth % H_;
    int n0   = blockIdx.x * 128;
    size_t gbase = (size_t)bt * N_ * D_ + (size_t)h * HD_;

    #pragma unroll
    for (int r = 0; r < 4; r++) {
        int e    = tid + r * 256;
        int row  = e >> 3;
        int cseg = e & 7;
        int gn = n0 + row;
        const __half* src = q + gbase + (size_t)(gn < N_ ? gn : 0) * D_ + cseg * 8;
        uint32_t dst = sQ + (row * PB + cseg * 8) * 2;
        int sz = (gn < N_) ? 16 : 0;
        asm volatile("cp.async.ca.shared.global [%0], [%1], 16, %2;"
                     :: "r"(dst), "l"(src), "r"(sz));
    }
    auto load_kv = [&](int m0, int buf) {
        uint32_t kdst0 = sK0 + buf * 64 * PB * 2;
        uint32_t vdst0 = sV0 + buf * 64 * PB * 2;
        #pragma unroll
        for (int r = 0; r < 2; r++) {
            int e    = tid + r * 256;
            int row  = e >> 3;
            int cseg = e & 7;
            int gm = m0 + row;
            size_t goff = gbase + (size_t)(gm < N_ ? gm : 0) * D_ + cseg * 8;
            int sz = (gm < N_) ? 16 : 0;
            uint32_t kd = kdst0 + (row * PB + cseg * 8) * 2;
            uint32_t vd = vdst0 + (row * PB + cseg * 8) * 2;
            asm volatile("cp.async.ca.shared.global [%0], [%1], 16, %2;"
                         :: "r"(kd), "l"(k + goff), "r"(sz));
            asm volatile("cp.async.ca.shared.global [%0], [%1], 16, %2;"
                         :: "r"(vd), "l"(v + goff), "r"(sz));
        }
        asm volatile("cp.async.commit_group;");
    };

    load_kv(0, 0);

    float oacc[8][4];
    #pragma unroll
    for (int ni = 0; ni < 8; ni++)
        #pragma unroll
        for (int r = 0; r < 4; r++) oacc[ni][r] = 0.f;
    float rs[2] = {0.f, 0.f};

    int qrow_frag = wid * 16 + (lane >> 2);
    int arow  = wid * 16 + (lane & 15);
    int acol8 = (lane >> 4) * 8;
    int brow  = (lane & 7) + ((lane >> 3) & 1) * 8;
    int bcol8 = (lane >> 4) * 8;
    int l4 = lane & 3;

    int buf = 0;
    for (int it = 0; it < 5; it++) {
        int m0 = it * 64;
        if (it < 4) load_kv(m0 + 64, buf ^ 1);
        if (it < 4) asm volatile("cp.async.wait_group 1;");
        else        asm volatile("cp.async.wait_group 0;");
        __syncthreads();

        uint32_t sK = sK0 + buf * 64 * PB * 2;
        uint32_t sV = sV0 + buf * 64 * PB * 2;

        float sacc[8][4];
        #pragma unroll
        for (int ni = 0; ni < 8; ni++)
            #pragma unroll
            for (int r = 0; r < 4; r++) sacc[ni][r] = 0.f;
        #pragma unroll
        for (int kk = 0; kk < 4; kk++) {
            uint32_t a[4];
            uint32_t sa = sQ + (arow * PB + kk * 16 + acol8) * 2;
            asm volatile(
                "ldmatrix.sync.aligned.m8n8.x4.shared.b16 {%0,%1,%2,%3}, [%4];"
                : "=r"(a[0]), "=r"(a[1]), "=r"(a[2]), "=r"(a[3]) : "r"(sa));
            uint32_t bfr[4][4];
            #pragma unroll
            for (int t = 0; t < 4; t++) {
                uint32_t sbb = sK + ((t * 16 + brow) * PB + kk * 16 + bcol8) * 2;
                asm volatile(
                    "ldmatrix.sync.aligned.m8n8.x4.shared.b16 {%0,%1,%2,%3}, [%4];"
                    : "=r"(bfr[t][0]), "=r"(bfr[t][1]), "=r"(bfr[t][2]), "=r"(bfr[t][3])
                    : "r"(sbb));
            }
            #pragma unroll
            for (int ni = 0; ni < 8; ni++) {
                uint32_t b0 = bfr[ni >> 1][ni & 1];
                uint32_t b1 = bfr[ni >> 1][(ni & 1) + 2];
                asm volatile(
                    "mma.sync.aligned.m16n8k16.row.col.f32.f16.f16.f32 "
                    "{%0,%1,%2,%3}, {%4,%5,%6,%7}, {%8,%9}, {%0,%1,%2,%3};"
                    : "+f"(sacc[ni][0]), "+f"(sacc[ni][1]),
                      "+f"(sacc[ni][2]), "+f"(sacc[ni][3])
                    : "r"(a[0]), "r"(a[1]), "r"(a[2]), "r"(a[3]),
                      "r"(b0), "r"(b1));
            }
        }

        // P = exp2(s * m')  (m' premultiplied by 0.125*log2e)
        #pragma unroll
        for (int u = 0; u < 2; u++) {
            int rloc = qrow_frag + u * 8;
            int gr   = n0 + rloc;
            const float* mrow = mask + (size_t)(gr < N_ ? gr : 0) * MP + m0;
            float local = 0.f;
            #pragma unroll
            for (int ni = 0; ni < 8; ni++) {
                int c = ni * 8 + 2 * l4;
                float2 mv = *(const float2*)(mrow + c);
                float e0 = 0.f, e1 = 0.f;
                if (m0 + c     < N_) e0 = ex2f(sacc[ni][2 * u + 0] * mv.x);
                if (m0 + c + 1 < N_) e1 = ex2f(sacc[ni][2 * u + 1] * mv.y);
                local += e0 + e1;
                uint32_t pk = pack_f16x2(e0, e1);
                uint32_t pd = sP + (rloc * PB + c) * 2;
                asm volatile("st.shared.b32 [%0], %1;" :: "r"(pd), "r"(pk));
            }
            rs[u] += local;
        }
        __syncwarp();

        #pragma unroll
        for (int kk = 0; kk < 4; kk++) {
            uint32_t a[4];
            uint32_t sa = sP + (arow * PB + kk * 16 + acol8) * 2;
            asm volatile(
                "ldmatrix.sync.aligned.m8n8.x4.shared.b16 {%0,%1,%2,%3}, [%4];"
                : "=r"(a[0]), "=r"(a[1]), "=r"(a[2]), "=r"(a[3]) : "r"(sa));
            uint32_t bfr[4][4];
            #pragma unroll
            for (int t = 0; t < 4; t++) {
                uint32_t sbb = sV + ((kk * 16 + brow) * PB + t * 16 + bcol8) * 2;
                asm volatile(
                    "ldmatrix.sync.aligned.m8n8.x4.trans.shared.b16 {%0,%1,%2,%3}, [%4];"
                    : "=r"(bfr[t][0]), "=r"(bfr[t][1]), "=r"(bfr[t][2]), "=r"(bfr[t][3])
                    : "r"(sbb));
            }
            #pragma unroll
            for (int ni = 0; ni < 8; ni++) {
                uint32_t b0 = bfr[ni >> 1][(ni & 1) * 2];
                uint32_t b1 = bfr[ni >> 1][(ni & 1) * 2 + 1];
                asm volatile(
                    "mma.sync.aligned.m16n8k16.row.col.f32.f16.f16.f32 "
                    "{%0,%1,%2,%3}, {%4,%5,%6,%7}, {%8,%9}, {%0,%1,%2,%3};"
                    : "+f"(oacc[ni][0]), "+f"(oacc[ni][1]),
                      "+f"(oacc[ni][2]), "+f"(oacc[ni][3])
                    : "r"(a[0]), "r"(a[1]), "r"(a[2]), "r"(a[3]),
                      "r"(b0), "r"(b1));
            }
        }
        __syncthreads();
        buf ^= 1;
    }

    // epilogue: normalize, store fp16
    #pragma unroll
    for (int u = 0; u < 2; u++) {
        rs[u] += __shfl_xor_sync(0xffffffffu, rs[u], 1);
        rs[u] += __shfl_xor_sync(0xffffffffu, rs[u], 2);
        int gr = n0 + qrow_frag + u * 8;
        if (gr >= N_) continue;
        float inv = 1.f / rs[u];
        #pragma unroll
        for (int ni = 0; ni < 8; ni++) {
            int dc = ni * 8 + 2 * l4;
            *(uint32_t*)(out + gbase + (size_t)gr * D_ + dc) =
                pack_f16x2(oacc[ni][2 * u] * inv, oacc[ni][2 * u + 1] * inv);
        }
    }
}

// ---------------- launch ----------------
extern "C" void kernel_launch(void* const* d_in, const int* in_sizes, int n_in,
                              void* d_out, int out_size)
{
    const float* query = (const float*)d_in[0];
    const float* key   = (const float*)d_in[1];
    const float* value = (const float*)d_in[2];
    const float* sem   = (const float*)d_in[3];
    const float* Wq    = (const float*)d_in[4];
    const float* bq    = (const float*)d_in[5];
    const float* Wk    = (const float*)d_in[6];
    const float* bk    = (const float*)d_in[7];
    const float* Wv    = (const float*)d_in[8];
    const float* bv    = (const float*)d_in[9];
    const float* Wo    = (const float*)d_in[10];
    const float* bo    = (const float*)d_in[11];
    float* out = (float*)d_out;

    float *mask_p;
    __half *inq_p, *ink_p, *inv_p, *qh_p, *kh_p, *vh_p, *oh_p, *wt_p;
    cudaGetSymbolAddress((void**)&mask_p, g_mask);
    cudaGetSymbolAddress((void**)&inq_p,  g_inq);
    cudaGetSymbolAddress((void**)&ink_p,  g_ink);
    cudaGetSymbolAddress((void**)&inv_p,  g_inv);
    cudaGetSymbolAddress((void**)&qh_p,   g_qh);
    cudaGetSymbolAddress((void**)&kh_p,   g_kh);
    cudaGetSymbolAddress((void**)&vh_p,   g_vh);
    cudaGetSymbolAddress((void**)&oh_p,   g_oh);
    cudaGetSymbolAddress((void**)&wt_p,   g_wt);

    static bool attr_set = false;
    if (!attr_set) {
        cudaFuncSetAttribute(attn_mma_kernel,
                             cudaFuncAttributeMaxDynamicSharedMemorySize, ATTN_SMEM);
        cudaFuncSetAttribute(gemm_bias_f16_kernel,
                             cudaFuncAttributeMaxDynamicSharedMemorySize, GEMM_SMEM);
        attr_set = true;
    }

    mask_softmax_kernel<<<N_, 256>>>(sem, mask_p);

    dim3 tg(D_ / 32, D_ / 32, 4);
    transpose_w_kernel<<<tg, dim3(32, 8)>>>(Wq, Wk, Wv, Wo, wt_p);

    // bulk fp32 -> fp16 input conversion
    dim3 cg((M_TOT * D_ / 8 + 255) / 256, 3);
    cvt_f16_kernel<<<cg, 256>>>(query, key, value, inq_p, ink_p, inv_p);

    // fused Q/K/V projections (fp16 A via cp.async) -> fp16 outputs
    dim3 g3(D_ / 128, (M_TOT + 127) / 128, 3);
    gemm_bias_f16_kernel<<<g3, 256, GEMM_SMEM>>>(
        inq_p, ink_p, inv_p, wt_p, bq, bk, bv, qh_p, kh_p, vh_p, M_TOT, 1);

    dim3 ga((N_ + 127) / 128, B_ * T_ * H_);
    attn_mma_kernel<<<ga, 256, ATTN_SMEM>>>(qh_p, kh_p, vh_p, mask_p, oh_p);

    // output projection (fp16 A, fp32 out)
    dim3 g1(D_ / 128, (M_TOT + 127) / 128, 1);
    gemm_bias_f16_kernel<<<g1, 256, GEMM_SMEM>>>(
        oh_p, oh_p, oh_p, wt_p + 3 * (size_t)D_ * D_, bo, bo, bo,
        out, out, out, M_TOT, 0);
}

// round 13
// speedup vs baseline: 1.1326x; 1.1326x over previous
#include <cuda_runtime.h>
#include <cuda_fp16.h>
#include <math.h>
#include <cstdint>

#define B_   8
#define T_   12
#define N_   307
#define D_   512
#define H_   8
#define HD_  64
#define M_TOT (B_*T_*N_)   // 29472
#define MP   320           // padded mask row pitch

// ---------------- device scratch (allocation-free rule) ----------------
__device__ float g_mask[N_*MP];            // premultiplied by 0.125*log2(e)
__device__ __half g_qh[M_TOT*D_];          // projected q/k/v (fp16)
__device__ __half g_kh[M_TOT*D_];
__device__ __half g_vh[M_TOT*D_];
__device__ __half g_oh[M_TOT*D_];          // attention output (fp16)
__device__ __half g_wt[4*D_*D_];           // transposed fp16 weights [N][K]

__device__ __forceinline__ uint32_t pack_f16x2(float lo, float hi) {
    uint32_t r;
    asm("cvt.rn.f16x2.f32 %0, %1, %2;" : "=r"(r) : "f"(hi), "f"(lo));
    return r;
}
__device__ __forceinline__ float ex2f(float x) {
    float r;
    asm("ex2.approx.f32 %0, %1;" : "=f"(r) : "f"(x));
    return r;
}

// ---------------- mask = row-softmax * (0.125*log2e), padded pitch -----
__global__ void mask_softmax_kernel(const float* __restrict__ sem,
                                    float* __restrict__ mask)
{
    int row = blockIdx.x;
    int tid = threadIdx.x;
    __shared__ float red[256];
    const float* x = sem + (size_t)row * N_;
    float v0 = (tid       < N_) ? x[tid]       : -INFINITY;
    float v1 = (tid + 256 < N_) ? x[tid + 256] : -INFINITY;
    red[tid] = fmaxf(v0, v1);
    __syncthreads();
    for (int s = 128; s > 0; s >>= 1) {
        if (tid < s) red[tid] = fmaxf(red[tid], red[tid + s]);
        __syncthreads();
    }
    float rowmax = red[0];
    __syncthreads();
    float e0 = (tid       < N_) ? __expf(v0 - rowmax) : 0.f;
    float e1 = (tid + 256 < N_) ? __expf(v1 - rowmax) : 0.f;
    red[tid] = e0 + e1;
    __syncthreads();
    for (int s = 128; s > 0; s >>= 1) {
        if (tid < s) red[tid] += red[tid + s];
        __syncthreads();
    }
    float inv = 0.180336880f / red[0];   // 0.125 * log2(e) / sum
    if (tid       < N_) mask[(size_t)row * MP + tid]       = e0 * inv;
    if (tid + 256 < N_) mask[(size_t)row * MP + tid + 256] = e1 * inv;
    if (tid == 0)
        for (int c = N_; c < MP; c++) mask[(size_t)row * MP + c] = 0.f;
}

// ---------------- W -> W^T (fp16), 4 matrices ----------------
__global__ void transpose_w_kernel(const float* __restrict__ w0,
                                   const float* __restrict__ w1,
                                   const float* __restrict__ w2,
                                   const float* __restrict__ w3,
                                   __half* __restrict__ wt)
{
    __shared__ float t[32][33];
    int z  = blockIdx.z;
    const float* src = (z == 0) ? w0 : (z == 1) ? w1 : (z == 2) ? w2 : w3;
    __half* dst = wt + (size_t)z * D_ * D_;
    int tx = threadIdx.x, ty = threadIdx.y;
    int bx = blockIdx.x * 32, by = blockIdx.y * 32;
    #pragma unroll
    for (int i = 0; i < 32; i += 8)
        t[ty + i][tx] = src[(size_t)(by + ty + i) * D_ + bx + tx];
    __syncthreads();
    #pragma unroll
    for (int i = 0; i < 32; i += 8)
        dst[(size_t)(bx + ty + i) * D_ + by + tx] = __float2half(t[tx][ty + i]);
}

// ---------------- fp16 mma GEMM (m16n8k16), R11 pipeline ---------------
// tiles: 128x128x64, 256 thr = 8 warps (2m x 4n). A/W smem fp16 pitch 72.
// F16_IN=false: A fp32 global -> LDG + cvt + STS. F16_IN=true: A cp.async.
#define GP 72
#define TILE_H (128 * GP)                 // halves per tile
#define GEMM_SMEM (4 * TILE_H * 2)        // 2 bufs x (A + W) = 73728 B

template<bool F16_IN, bool F16_OUT>
__global__ __launch_bounds__(256, 2)
void gemm_bias_f16_kernel(const void* __restrict__ A0, const void* __restrict__ A1,
                          const void* __restrict__ A2, const __half* __restrict__ WtB,
                          const float* __restrict__ b0p, const float* __restrict__ b1p,
                          const float* __restrict__ b2p,
                          void* __restrict__ C0, void* __restrict__ C1,
                          void* __restrict__ C2, int M)
{
    extern __shared__ __half gsh[];
    int z = blockIdx.z;
    const void* Av     = (z == 0) ? A0 : (z == 1) ? A1 : A2;
    const __half* Wt   = WtB + (size_t)z * D_ * D_;
    const float* bias  = (z == 0) ? b0p : (z == 1) ? b1p : b2p;
    void* Cv           = (z == 0) ? C0 : (z == 1) ? C1 : C2;

    int tid  = threadIdx.x;
    int lane = tid & 31;
    int wid  = tid >> 5;
    int warp_m = wid & 1;
    int warp_n = wid >> 1;
    int m0 = blockIdx.y * 128;
    int n0 = blockIdx.x * 128;

    float acc[4][4][4];
    #pragma unroll
    for (int mi = 0; mi < 4; mi++)
        #pragma unroll
        for (int ni = 0; ni < 4; ni++)
            #pragma unroll
            for (int r = 0; r < 4; r++) acc[mi][ni][r] = 0.f;

    float4 stA[4][2];

    // fp32-A path: stage to regs
    auto ldg_A = [&](int k0) {
        const float* A = (const float*)Av;
        #pragma unroll
        for (int r = 0; r < 4; r++) {
            int e   = tid + r * 256;
            int row = e >> 3;
            int seg = e & 7;
            int gm = m0 + row;
            if (gm < M) {
                const float* src = A + (size_t)gm * D_ + k0 + seg * 8;
                stA[r][0] = *(const float4*)(src);
                stA[r][1] = *(const float4*)(src + 4);
            } else {
                stA[r][0] = make_float4(0.f, 0.f, 0.f, 0.f);
                stA[r][1] = make_float4(0.f, 0.f, 0.f, 0.f);
            }
        }
    };
    auto sts_A = [&](int b) {
        __half* Ab = gsh + b * 2 * TILE_H;
        #pragma unroll
        for (int r = 0; r < 4; r++) {
            int e   = tid + r * 256;
            int row = e >> 3;
            int seg = e & 7;
            uint4 p;
            p.x = pack_f16x2(stA[r][0].x, stA[r][0].y);
            p.y = pack_f16x2(stA[r][0].z, stA[r][0].w);
            p.z = pack_f16x2(stA[r][1].x, stA[r][1].y);
            p.w = pack_f16x2(stA[r][1].z, stA[r][1].w);
            *(uint4*)(Ab + row * GP + seg * 8) = p;
        }
    };
    // fp16-A path: cp.async
    auto cpa_A = [&](int b, int k0) {
        const __half* A = (const __half*)Av;
        __half* Ab = gsh + b * 2 * TILE_H;
        #pragma unroll
        for (int r = 0; r < 4; r++) {
            int e   = tid + r * 256;
            int row = e >> 3;
            int seg = e & 7;
            int gm = m0 + row;
            const __half* src = A + (size_t)(gm < M ? gm : 0) * D_ + k0 + seg * 8;
            int sz = (gm < M) ? 16 : 0;
            uint32_t dst = (uint32_t)__cvta_generic_to_shared(Ab + row * GP + seg * 8);
            asm volatile("cp.async.ca.shared.global [%0], [%1], 16, %2;"
                         :: "r"(dst), "l"(src), "r"(sz));
        }
    };
    auto cpa_W = [&](int b, int k0) {
        __half* Wb = gsh + b * 2 * TILE_H + TILE_H;
        #pragma unroll
        for (int r = 0; r < 4; r++) {
            int e   = tid + r * 256;
            int row = e >> 3;
            int seg = e & 7;
            uint32_t dst = (uint32_t)__cvta_generic_to_shared(Wb + row * GP + seg * 8);
            const __half* src = Wt + (size_t)(n0 + row) * D_ + k0 + seg * 8;
            asm volatile("cp.async.ca.shared.global [%0], [%1], 16;"
                         :: "r"(dst), "l"(src));
        }
        asm volatile("cp.async.commit_group;");
    };

    if (F16_IN) { cpa_A(0, 0); cpa_W(0, 0); }
    else        { ldg_A(0); cpa_W(0, 0); sts_A(0); }
    asm volatile("cp.async.wait_group 0;");
    __syncthreads();

    int arow_sub = lane & 15;
    int acol8    = (lane >> 4) * 8;
    int brow_sub = (lane & 7) + ((lane >> 3) & 1) * 8;
    int bcol8    = (lane >> 4) * 8;

    int buf = 0;
    for (int k0 = 0; k0 < D_; k0 += 64) {
        bool last = (k0 == D_ - 64);
        if (!last) {
            if (F16_IN) { cpa_A(buf ^ 1, k0 + 64); cpa_W(buf ^ 1, k0 + 64); }
            else        { ldg_A(k0 + 64); cpa_W(buf ^ 1, k0 + 64); }
        }

        __half* Ab = gsh + buf * 2 * TILE_H;
        __half* Wb = Ab + TILE_H;
        #pragma unroll
        for (int kk = 0; kk < 4; kk++) {
            uint32_t a[4][4];
            #pragma unroll
            for (int mi = 0; mi < 4; mi++) {
                uint32_t sa = (uint32_t)__cvta_generic_to_shared(
                    Ab + (warp_m * 64 + mi * 16 + arow_sub) * GP + kk * 16 + acol8);
                asm volatile(
                    "ldmatrix.sync.aligned.m8n8.x4.shared.b16 {%0,%1,%2,%3}, [%4];"
                    : "=r"(a[mi][0]), "=r"(a[mi][1]), "=r"(a[mi][2]), "=r"(a[mi][3])
                    : "r"(sa));
            }
            uint32_t bfr[2][4];
            #pragma unroll
            for (int t = 0; t < 2; t++) {
                uint32_t sbb = (uint32_t)__cvta_generic_to_shared(
                    Wb + (warp_n * 32 + t * 16 + brow_sub) * GP + kk * 16 + bcol8);
                asm volatile(
                    "ldmatrix.sync.aligned.m8n8.x4.shared.b16 {%0,%1,%2,%3}, [%4];"
                    : "=r"(bfr[t][0]), "=r"(bfr[t][1]), "=r"(bfr[t][2]), "=r"(bfr[t][3])
                    : "r"(sbb));
            }
            #pragma unroll
            for (int ni = 0; ni < 4; ni++) {
                uint32_t b0 = bfr[ni >> 1][ni & 1];
                uint32_t b1 = bfr[ni >> 1][(ni & 1) + 2];
                #pragma unroll
                for (int mi = 0; mi < 4; mi++) {
                    asm volatile(
                        "mma.sync.aligned.m16n8k16.row.col.f32.f16.f16.f32 "
                        "{%0,%1,%2,%3}, {%4,%5,%6,%7}, {%8,%9}, {%0,%1,%2,%3};"
                        : "+f"(acc[mi][ni][0]), "+f"(acc[mi][ni][1]),
                          "+f"(acc[mi][ni][2]), "+f"(acc[mi][ni][3])
                        : "r"(a[mi][0]), "r"(a[mi][1]), "r"(a[mi][2]), "r"(a[mi][3]),
                          "r"(b0), "r"(b1));
                }
            }
        }
        if (!last) {
            if (!F16_IN) sts_A(buf ^ 1);
            asm volatile("cp.async.wait_group 0;");
            __syncthreads();
            buf ^= 1;
        }
    }

    int crow = m0 + warp_m * 64 + (lane >> 2);
    int ccol0 = n0 + warp_n * 32 + 2 * (lane & 3);
    #pragma unroll
    for (int mi = 0; mi < 4; mi++) {
        int r0 = crow + mi * 16;
        #pragma unroll
        for (int ni = 0; ni < 4; ni++) {
            int cc = ccol0 + ni * 8;
            float bb0 = bias[cc], bb1 = bias[cc + 1];
            if (F16_OUT) {
                __half* C = (__half*)Cv;
                if (r0 < M)
                    *(uint32_t*)(C + (size_t)r0 * D_ + cc) =
                        pack_f16x2(acc[mi][ni][0] + bb0, acc[mi][ni][1] + bb1);
                if (r0 + 8 < M)
                    *(uint32_t*)(C + (size_t)(r0 + 8) * D_ + cc) =
                        pack_f16x2(acc[mi][ni][2] + bb0, acc[mi][ni][3] + bb1);
            } else {
                float* C = (float*)Cv;
                if (r0 < M) {
                    float2 o = make_float2(acc[mi][ni][0] + bb0, acc[mi][ni][1] + bb1);
                    *(float2*)(C + (size_t)r0 * D_ + cc) = o;
                }
                if (r0 + 8 < M) {
                    float2 o = make_float2(acc[mi][ni][2] + bb0, acc[mi][ni][3] + bb1);
                    *(float2*)(C + (size_t)(r0 + 8) * D_ + cc) = o;
                }
            }
        }
    }
}

// ---------------- fp16 flash attention (m16n8k16), fp16 out, ex2 mask --
#define PB 72
#define ATTN_SMEM ((2*128*PB + 4*64*PB) * 2)   // 73728 B

__global__ __launch_bounds__(256, 2)
void attn_mma_kernel(const __half* __restrict__ q,
                     const __half* __restrict__ k,
                     const __half* __restrict__ v,
                     const float* __restrict__ mask,
                     __half* __restrict__ out)
{
    extern __shared__ char smc[];
    uint32_t sb = (uint32_t)__cvta_generic_to_shared(smc);
    const uint32_t sQ = sb;
    const uint32_t sP = sb + 128 * PB * 2;
    const uint32_t sK0 = sb + 2 * 128 * PB * 2;
    const uint32_t sV0 = sK0 + 2 * 64 * PB * 2;

    int tid  = threadIdx.x;
    int lane = tid & 31;
    int wid  = tid >> 5;
    int bth  = blockIdx.y;
    int bt   = bth / H_;
    int h    = bth % H_;
    int n0   = blockIdx.x * 128;
    size_t gbase = (size_t)bt * N_ * D_ + (size_t)h * HD_;

    #pragma unroll
    for (int r = 0; r < 4; r++) {
        int e    = tid + r * 256;
        int row  = e >> 3;
        int cseg = e & 7;
        int gn = n0 + row;
        const __half* src = q + gbase + (size_t)(gn < N_ ? gn : 0) * D_ + cseg * 8;
        uint32_t dst = sQ + (row * PB + cseg * 8) * 2;
        int sz = (gn < N_) ? 16 : 0;
        asm volatile("cp.async.ca.shared.global [%0], [%1], 16, %2;"
                     :: "r"(dst), "l"(src), "r"(sz));
    }
    auto load_kv = [&](int m0, int buf) {
        uint32_t kdst0 = sK0 + buf * 64 * PB * 2;
        uint32_t vdst0 = sV0 + buf * 64 * PB * 2;
        #pragma unroll
        for (int r = 0; r < 2; r++) {
            int e    = tid + r * 256;
            int row  = e >> 3;
            int cseg = e & 7;
            int gm = m0 + row;
            size_t goff = gbase + (size_t)(gm < N_ ? gm : 0) * D_ + cseg * 8;
            int sz = (gm < N_) ? 16 : 0;
            uint32_t kd = kdst0 + (row * PB + cseg * 8) * 2;
            uint32_t vd = vdst0 + (row * PB + cseg * 8) * 2;
            asm volatile("cp.async.ca.shared.global [%0], [%1], 16, %2;"
                         :: "r"(kd), "l"(k + goff), "r"(sz));
            asm volatile("cp.async.ca.shared.global [%0], [%1], 16, %2;"
                         :: "r"(vd), "l"(v + goff), "r"(sz));
        }
        asm volatile("cp.async.commit_group;");
    };

    load_kv(0, 0);

    float oacc[8][4];
    #pragma unroll
    for (int ni = 0; ni < 8; ni++)
        #pragma unroll
        for (int r = 0; r < 4; r++) oacc[ni][r] = 0.f;
    float rs[2] = {0.f, 0.f};

    int qrow_frag = wid * 16 + (lane >> 2);
    int arow  = wid * 16 + (lane & 15);
    int acol8 = (lane >> 4) * 8;
    int brow  = (lane & 7) + ((lane >> 3) & 1) * 8;
    int bcol8 = (lane >> 4) * 8;
    int l4 = lane & 3;

    int buf = 0;
    for (int it = 0; it < 5; it++) {
        int m0 = it * 64;
        if (it < 4) load_kv(m0 + 64, buf ^ 1);
        if (it < 4) asm volatile("cp.async.wait_group 1;");
        else        asm volatile("cp.async.wait_group 0;");
        __syncthreads();

        uint32_t sK = sK0 + buf * 64 * PB * 2;
        uint32_t sV = sV0 + buf * 64 * PB * 2;

        float sacc[8][4];
        #pragma unroll
        for (int ni = 0; ni < 8; ni++)
            #pragma unroll
            for (int r = 0; r < 4; r++) sacc[ni][r] = 0.f;
        #pragma unroll
        for (int kk = 0; kk < 4; kk++) {
            uint32_t a[4];
            uint32_t sa = sQ + (arow * PB + kk * 16 + acol8) * 2;
            asm volatile(
                "ldmatrix.sync.aligned.m8n8.x4.shared.b16 {%0,%1,%2,%3}, [%4];"
                : "=r"(a[0]), "=r"(a[1]), "=r"(a[2]), "=r"(a[3]) : "r"(sa));
            uint32_t bfr[4][4];
            #pragma unroll
            for (int t = 0; t < 4; t++) {
                uint32_t sbb = sK + ((t * 16 + brow) * PB + kk * 16 + bcol8) * 2;
                asm volatile(
                    "ldmatrix.sync.aligned.m8n8.x4.shared.b16 {%0,%1,%2,%3}, [%4];"
                    : "=r"(bfr[t][0]), "=r"(bfr[t][1]), "=r"(bfr[t][2]), "=r"(bfr[t][3])
                    : "r"(sbb));
            }
            #pragma unroll
            for (int ni = 0; ni < 8; ni++) {
                uint32_t b0 = bfr[ni >> 1][ni & 1];
                uint32_t b1 = bfr[ni >> 1][(ni & 1) + 2];
                asm volatile(
                    "mma.sync.aligned.m16n8k16.row.col.f32.f16.f16.f32 "
                    "{%0,%1,%2,%3}, {%4,%5,%6,%7}, {%8,%9}, {%0,%1,%2,%3};"
                    : "+f"(sacc[ni][0]), "+f"(sacc[ni][1]),
                      "+f"(sacc[ni][2]), "+f"(sacc[ni][3])
                    : "r"(a[0]), "r"(a[1]), "r"(a[2]), "r"(a[3]),
                      "r"(b0), "r"(b1));
            }
        }

        // P = exp2(s * m')  (m' premultiplied by 0.125*log2e)
        #pragma unroll
        for (int u = 0; u < 2; u++) {
            int rloc = qrow_frag + u * 8;
            int gr   = n0 + rloc;
            const float* mrow = mask + (size_t)(gr < N_ ? gr : 0) * MP + m0;
            float local = 0.f;
            #pragma unroll
            for (int ni = 0; ni < 8; ni++) {
                int c = ni * 8 + 2 * l4;
                float2 mv = *(const float2*)(mrow + c);
                float e0 = 0.f, e1 = 0.f;
                if (m0 + c     < N_) e0 = ex2f(sacc[ni][2 * u + 0] * mv.x);
                if (m0 + c + 1 < N_) e1 = ex2f(sacc[ni][2 * u + 1] * mv.y);
                local += e0 + e1;
                uint32_t pk = pack_f16x2(e0, e1);
                uint32_t pd = sP + (rloc * PB + c) * 2;
                asm volatile("st.shared.b32 [%0], %1;" :: "r"(pd), "r"(pk));
            }
            rs[u] += local;
        }
        __syncwarp();

        #pragma unroll
        for (int kk = 0; kk < 4; kk++) {
            uint32_t a[4];
            uint32_t sa = sP + (arow * PB + kk * 16 + acol8) * 2;
            asm volatile(
                "ldmatrix.sync.aligned.m8n8.x4.shared.b16 {%0,%1,%2,%3}, [%4];"
                : "=r"(a[0]), "=r"(a[1]), "=r"(a[2]), "=r"(a[3]) : "r"(sa));
            uint32_t bfr[4][4];
            #pragma unroll
            for (int t = 0; t < 4; t++) {
                uint32_t sbb = sV + ((kk * 16 + brow) * PB + t * 16 + bcol8) * 2;
                asm volatile(
                    "ldmatrix.sync.aligned.m8n8.x4.trans.shared.b16 {%0,%1,%2,%3}, [%4];"
                    : "=r"(bfr[t][0]), "=r"(bfr[t][1]), "=r"(bfr[t][2]), "=r"(bfr[t][3])
                    : "r"(sbb));
            }
            #pragma unroll
            for (int ni = 0; ni < 8; ni++) {
                uint32_t b0 = bfr[ni >> 1][(ni & 1) * 2];
                uint32_t b1 = bfr[ni >> 1][(ni & 1) * 2 + 1];
                asm volatile(
                    "mma.sync.aligned.m16n8k16.row.col.f32.f16.f16.f32 "
                    "{%0,%1,%2,%3}, {%4,%5,%6,%7}, {%8,%9}, {%0,%1,%2,%3};"
                    : "+f"(oacc[ni][0]), "+f"(oacc[ni][1]),
                      "+f"(oacc[ni][2]), "+f"(oacc[ni][3])
                    : "r"(a[0]), "r"(a[1]), "r"(a[2]), "r"(a[3]),
                      "r"(b0), "r"(b1));
            }
        }
        __syncthreads();
        buf ^= 1;
    }

    // epilogue: normalize, store fp16
    #pragma unroll
    for (int u = 0; u < 2; u++) {
        rs[u] += __shfl_xor_sync(0xffffffffu, rs[u], 1);
        rs[u] += __shfl_xor_sync(0xffffffffu, rs[u], 2);
        int gr = n0 + qrow_frag + u * 8;
        if (gr >= N_) continue;
        float inv = 1.f / rs[u];
        #pragma unroll
        for (int ni = 0; ni < 8; ni++) {
            int dc = ni * 8 + 2 * l4;
            *(uint32_t*)(out + gbase + (size_t)gr * D_ + dc) =
                pack_f16x2(oacc[ni][2 * u] * inv, oacc[ni][2 * u + 1] * inv);
        }
    }
}

// ---------------- launch ----------------
extern "C" void kernel_launch(void* const* d_in, const int* in_sizes, int n_in,
                              void* d_out, int out_size)
{
    const float* query = (const float*)d_in[0];
    const float* key   = (const float*)d_in[1];
    const float* value = (const float*)d_in[2];
    const float* sem   = (const float*)d_in[3];
    const float* Wq    = (const float*)d_in[4];
    const float* bq    = (const float*)d_in[5];
    const float* Wk    = (const float*)d_in[6];
    const float* bk    = (const float*)d_in[7];
    const float* Wv    = (const float*)d_in[8];
    const float* bv    = (const float*)d_in[9];
    const float* Wo    = (const float*)d_in[10];
    const float* bo    = (const float*)d_in[11];
    float* out = (float*)d_out;

    float *mask_p;
    __half *qh_p, *kh_p, *vh_p, *oh_p, *wt_p;
    cudaGetSymbolAddress((void**)&mask_p, g_mask);
    cudaGetSymbolAddress((void**)&qh_p,   g_qh);
    cudaGetSymbolAddress((void**)&kh_p,   g_kh);
    cudaGetSymbolAddress((void**)&vh_p,   g_vh);
    cudaGetSymbolAddress((void**)&oh_p,   g_oh);
    cudaGetSymbolAddress((void**)&wt_p,   g_wt);

    static bool attr_set = false;
    if (!attr_set) {
        cudaFuncSetAttribute(attn_mma_kernel,
                             cudaFuncAttributeMaxDynamicSharedMemorySize, ATTN_SMEM);
        cudaFuncSetAttribute(gemm_bias_f16_kernel<false, true>,
                             cudaFuncAttributeMaxDynamicSharedMemorySize, GEMM_SMEM);
        cudaFuncSetAttribute(gemm_bias_f16_kernel<true, false>,
                             cudaFuncAttributeMaxDynamicSharedMemorySize, GEMM_SMEM);
        attr_set = true;
    }

    mask_softmax_kernel<<<N_, 256>>>(sem, mask_p);

    dim3 tg(D_ / 32, D_ / 32, 4);
    transpose_w_kernel<<<tg, dim3(32, 8)>>>(Wq, Wk, Wv, Wo, wt_p);

    // fused Q/K/V projections (fp32 A in-kernel cvt) -> fp16 outputs
    dim3 g3(D_ / 128, (M_TOT + 127) / 128, 3);
    gemm_bias_f16_kernel<false, true><<<g3, 256, GEMM_SMEM>>>(
        query, key, value, wt_p, bq, bk, bv, qh_p, kh_p, vh_p, M_TOT);

    dim3 ga((N_ + 127) / 128, B_ * T_ * H_);
    attn_mma_kernel<<<ga, 256, ATTN_SMEM>>>(qh_p, kh_p, vh_p, mask_p, oh_p);

    // output projection (fp16 A via cp.async, fp32 out)
    dim3 g1(D_ / 128, (M_TOT + 127) / 128, 1);
    gemm_bias_f16_kernel<true, false><<<g1, 256, GEMM_SMEM>>>(
        oh_p, oh_p, oh_p, wt_p + 3 * (size_t)D_ * D_, bo, bo, bo,
        out, out, out, M_TOT);
}

// round 14
// speedup vs baseline: 1.2345x; 1.0900x over previous
#include <cuda_runtime.h>
#include <cuda_fp16.h>
#include <math.h>
#include <cstdint>

#define B_   8
#define T_   12
#define N_   307
#define D_   512
#define H_   8
#define HD_  64
#define M_TOT (B_*T_*N_)   // 29472
#define MP   320           // padded mask row pitch (halves)

// ---------------- device scratch (allocation-free rule) ----------------
__device__ __half g_maskh[N_*MP];          // fp16 mask, premul by 0.125*log2e
__device__ __half g_qh[M_TOT*D_];
__device__ __half g_kh[M_TOT*D_];
__device__ __half g_vh[M_TOT*D_];
__device__ __half g_oh[M_TOT*D_];
__device__ __half g_wt[4*D_*D_];           // transposed fp16 weights [N][K]

__device__ __forceinline__ uint32_t pack_f16x2(float lo, float hi) {
    uint32_t r;
    asm("cvt.rn.f16x2.f32 %0, %1, %2;" : "=r"(r) : "f"(hi), "f"(lo));
    return r;
}
__device__ __forceinline__ float ex2f(float x) {
    float r;
    asm("ex2.approx.f32 %0, %1;" : "=f"(r) : "f"(x));
    return r;
}

// ---------------- mask = row-softmax * (0.125*log2e) -> fp16 -----------
__global__ void mask_softmax_kernel(const float* __restrict__ sem,
                                    __half* __restrict__ mask)
{
    int row = blockIdx.x;
    int tid = threadIdx.x;
    __shared__ float red[256];
    const float* x = sem + (size_t)row * N_;
    float v0 = (tid       < N_) ? x[tid]       : -INFINITY;
    float v1 = (tid + 256 < N_) ? x[tid + 256] : -INFINITY;
    red[tid] = fmaxf(v0, v1);
    __syncthreads();
    for (int s = 128; s > 0; s >>= 1) {
        if (tid < s) red[tid] = fmaxf(red[tid], red[tid + s]);
        __syncthreads();
    }
    float rowmax = red[0];
    __syncthreads();
    float e0 = (tid       < N_) ? __expf(v0 - rowmax) : 0.f;
    float e1 = (tid + 256 < N_) ? __expf(v1 - rowmax) : 0.f;
    red[tid] = e0 + e1;
    __syncthreads();
    for (int s = 128; s > 0; s >>= 1) {
        if (tid < s) red[tid] += red[tid + s];
        __syncthreads();
    }
    float inv = 0.180336880f / red[0];   // 0.125 * log2(e) / sum
    if (tid       < N_) mask[(size_t)row * MP + tid]       = __float2half(e0 * inv);
    if (tid + 256 < N_) mask[(size_t)row * MP + tid + 256] = __float2half(e1 * inv);
    if (tid == 0)
        for (int c = N_; c < MP; c++) mask[(size_t)row * MP + c] = __float2half(0.f);
}

// ---------------- W -> W^T (fp16), 4 matrices ----------------
__global__ void transpose_w_kernel(const float* __restrict__ w0,
                                   const float* __restrict__ w1,
                                   const float* __restrict__ w2,
                                   const float* __restrict__ w3,
                                   __half* __restrict__ wt)
{
    __shared__ float t[32][33];
    int z  = blockIdx.z;
    const float* src = (z == 0) ? w0 : (z == 1) ? w1 : (z == 2) ? w2 : w3;
    __half* dst = wt + (size_t)z * D_ * D_;
    int tx = threadIdx.x, ty = threadIdx.y;
    int bx = blockIdx.x * 32, by = blockIdx.y * 32;
    #pragma unroll
    for (int i = 0; i < 32; i += 8)
        t[ty + i][tx] = src[(size_t)(by + ty + i) * D_ + bx + tx];
    __syncthreads();
    #pragma unroll
    for (int i = 0; i < 32; i += 8)
        dst[(size_t)(bx + ty + i) * D_ + by + tx] = __float2half(t[tx][ty + i]);
}

// ---------------- fp16 mma GEMM (m16n8k16), R13 pipeline (frozen) ------
#define GP 72
#define TILE_H (128 * GP)
#define GEMM_SMEM (4 * TILE_H * 2)        // 73728 B

template<bool F16_IN, bool F16_OUT>
__global__ __launch_bounds__(256, 2)
void gemm_bias_f16_kernel(const void* __restrict__ A0, const void* __restrict__ A1,
                          const void* __restrict__ A2, const __half* __restrict__ WtB,
                          const float* __restrict__ b0p, const float* __restrict__ b1p,
                          const float* __restrict__ b2p,
                          void* __restrict__ C0, void* __restrict__ C1,
                          void* __restrict__ C2, int M)
{
    extern __shared__ __half gsh[];
    int z = blockIdx.z;
    const void* Av     = (z == 0) ? A0 : (z == 1) ? A1 : A2;
    const __half* Wt   = WtB + (size_t)z * D_ * D_;
    const float* bias  = (z == 0) ? b0p : (z == 1) ? b1p : b2p;
    void* Cv           = (z == 0) ? C0 : (z == 1) ? C1 : C2;

    int tid  = threadIdx.x;
    int lane = tid & 31;
    int wid  = tid >> 5;
    int warp_m = wid & 1;
    int warp_n = wid >> 1;
    int m0 = blockIdx.y * 128;
    int n0 = blockIdx.x * 128;

    float acc[4][4][4];
    #pragma unroll
    for (int mi = 0; mi < 4; mi++)
        #pragma unroll
        for (int ni = 0; ni < 4; ni++)
            #pragma unroll
            for (int r = 0; r < 4; r++) acc[mi][ni][r] = 0.f;

    float4 stA[4][2];

    auto ldg_A = [&](int k0) {
        const float* A = (const float*)Av;
        #pragma unroll
        for (int r = 0; r < 4; r++) {
            int e   = tid + r * 256;
            int row = e >> 3;
            int seg = e & 7;
            int gm = m0 + row;
            if (gm < M) {
                const float* src = A + (size_t)gm * D_ + k0 + seg * 8;
                stA[r][0] = *(const float4*)(src);
                stA[r][1] = *(const float4*)(src + 4);
            } else {
                stA[r][0] = make_float4(0.f, 0.f, 0.f, 0.f);
                stA[r][1] = make_float4(0.f, 0.f, 0.f, 0.f);
            }
        }
    };
    auto sts_A = [&](int b) {
        __half* Ab = gsh + b * 2 * TILE_H;
        #pragma unroll
        for (int r = 0; r < 4; r++) {
            int e   = tid + r * 256;
            int row = e >> 3;
            int seg = e & 7;
            uint4 p;
            p.x = pack_f16x2(stA[r][0].x, stA[r][0].y);
            p.y = pack_f16x2(stA[r][0].z, stA[r][0].w);
            p.z = pack_f16x2(stA[r][1].x, stA[r][1].y);
            p.w = pack_f16x2(stA[r][1].z, stA[r][1].w);
            *(uint4*)(Ab + row * GP + seg * 8) = p;
        }
    };
    auto cpa_A = [&](int b, int k0) {
        const __half* A = (const __half*)Av;
        __half* Ab = gsh + b * 2 * TILE_H;
        #pragma unroll
        for (int r = 0; r < 4; r++) {
            int e   = tid + r * 256;
            int row = e >> 3;
            int seg = e & 7;
            int gm = m0 + row;
            const __half* src = A + (size_t)(gm < M ? gm : 0) * D_ + k0 + seg * 8;
            int sz = (gm < M) ? 16 : 0;
            uint32_t dst = (uint32_t)__cvta_generic_to_shared(Ab + row * GP + seg * 8);
            asm volatile("cp.async.ca.shared.global [%0], [%1], 16, %2;"
                         :: "r"(dst), "l"(src), "r"(sz));
        }
    };
    auto cpa_W = [&](int b, int k0) {
        __half* Wb = gsh + b * 2 * TILE_H + TILE_H;
        #pragma unroll
        for (int r = 0; r < 4; r++) {
            int e   = tid + r * 256;
            int row = e >> 3;
            int seg = e & 7;
            uint32_t dst = (uint32_t)__cvta_generic_to_shared(Wb + row * GP + seg * 8);
            const __half* src = Wt + (size_t)(n0 + row) * D_ + k0 + seg * 8;
            asm volatile("cp.async.ca.shared.global [%0], [%1], 16;"
                         :: "r"(dst), "l"(src));
        }
        asm volatile("cp.async.commit_group;");
    };

    if (F16_IN) { cpa_A(0, 0); cpa_W(0, 0); }
    else        { ldg_A(0); cpa_W(0, 0); sts_A(0); }
    asm volatile("cp.async.wait_group 0;");
    __syncthreads();

    int arow_sub = lane & 15;
    int acol8    = (lane >> 4) * 8;
    int brow_sub = (lane & 7) + ((lane >> 3) & 1) * 8;
    int bcol8    = (lane >> 4) * 8;

    int buf = 0;
    for (int k0 = 0; k0 < D_; k0 += 64) {
        bool last = (k0 == D_ - 64);
        if (!last) {
            if (F16_IN) { cpa_A(buf ^ 1, k0 + 64); cpa_W(buf ^ 1, k0 + 64); }
            else        { ldg_A(k0 + 64); cpa_W(buf ^ 1, k0 + 64); }
        }

        __half* Ab = gsh + buf * 2 * TILE_H;
        __half* Wb = Ab + TILE_H;
        #pragma unroll
        for (int kk = 0; kk < 4; kk++) {
            uint32_t a[4][4];
            #pragma unroll
            for (int mi = 0; mi < 4; mi++) {
                uint32_t sa = (uint32_t)__cvta_generic_to_shared(
                    Ab + (warp_m * 64 + mi * 16 + arow_sub) * GP + kk * 16 + acol8);
                asm volatile(
                    "ldmatrix.sync.aligned.m8n8.x4.shared.b16 {%0,%1,%2,%3}, [%4];"
                    : "=r"(a[mi][0]), "=r"(a[mi][1]), "=r"(a[mi][2]), "=r"(a[mi][3])
                    : "r"(sa));
            }
            uint32_t bfr[2][4];
            #pragma unroll
            for (int t = 0; t < 2; t++) {
                uint32_t sbb = (uint32_t)__cvta_generic_to_shared(
                    Wb + (warp_n * 32 + t * 16 + brow_sub) * GP + kk * 16 + bcol8);
                asm volatile(
                    "ldmatrix.sync.aligned.m8n8.x4.shared.b16 {%0,%1,%2,%3}, [%4];"
                    : "=r"(bfr[t][0]), "=r"(bfr[t][1]), "=r"(bfr[t][2]), "=r"(bfr[t][3])
                    : "r"(sbb));
            }
            #pragma unroll
            for (int ni = 0; ni < 4; ni++) {
                uint32_t b0 = bfr[ni >> 1][ni & 1];
                uint32_t b1 = bfr[ni >> 1][(ni & 1) + 2];
                #pragma unroll
                for (int mi = 0; mi < 4; mi++) {
                    asm volatile(
                        "mma.sync.aligned.m16n8k16.row.col.f32.f16.f16.f32 "
                        "{%0,%1,%2,%3}, {%4,%5,%6,%7}, {%8,%9}, {%0,%1,%2,%3};"
                        : "+f"(acc[mi][ni][0]), "+f"(acc[mi][ni][1]),
                          "+f"(acc[mi][ni][2]), "+f"(acc[mi][ni][3])
                        : "r"(a[mi][0]), "r"(a[mi][1]), "r"(a[mi][2]), "r"(a[mi][3]),
                          "r"(b0), "r"(b1));
                }
            }
        }
        if (!last) {
            if (!F16_IN) sts_A(buf ^ 1);
            asm volatile("cp.async.wait_group 0;");
            __syncthreads();
            buf ^= 1;
        }
    }

    int crow = m0 + warp_m * 64 + (lane >> 2);
    int ccol0 = n0 + warp_n * 32 + 2 * (lane & 3);
    #pragma unroll
    for (int mi = 0; mi < 4; mi++) {
        int r0 = crow + mi * 16;
        #pragma unroll
        for (int ni = 0; ni < 4; ni++) {
            int cc = ccol0 + ni * 8;
            float bb0 = bias[cc], bb1 = bias[cc + 1];
            if (F16_OUT) {
                __half* C = (__half*)Cv;
                if (r0 < M)
                    *(uint32_t*)(C + (size_t)r0 * D_ + cc) =
                        pack_f16x2(acc[mi][ni][0] + bb0, acc[mi][ni][1] + bb1);
                if (r0 + 8 < M)
                    *(uint32_t*)(C + (size_t)(r0 + 8) * D_ + cc) =
                        pack_f16x2(acc[mi][ni][2] + bb0, acc[mi][ni][3] + bb1);
            } else {
                float* C = (float*)Cv;
                if (r0 < M) {
                    float2 o = make_float2(acc[mi][ni][0] + bb0, acc[mi][ni][1] + bb1);
                    *(float2*)(C + (size_t)r0 * D_ + cc) = o;
                }
                if (r0 + 8 < M) {
                    float2 o = make_float2(acc[mi][ni][2] + bb0, acc[mi][ni][3] + bb1);
                    *(float2*)(C + (size_t)(r0 + 8) * D_ + cc) = o;
                }
            }
        }
    }
}

// ---------------- fp16 flash attention: smem mask + mma rowsum ---------
// pitch 72 halves everywhere (conflict-free ldmatrix and half2 LDS).
#define PB 72
#define SM_Q  0
#define SM_P  (128 * PB)
#define SM_K  (2 * 128 * PB)                 // [2][64*PB]
#define SM_V  (SM_K + 2 * 64 * PB)           // [2][64*PB]
#define SM_M  (SM_V + 2 * 64 * PB)           // [2][128*PB]
#define ATTN_SMEM ((SM_M + 2 * 128 * PB) * 2)   // 110592 B

__global__ __launch_bounds__(256, 2)
void attn_mma_kernel(const __half* __restrict__ q,
                     const __half* __restrict__ k,
                     const __half* __restrict__ v,
                     const __half* __restrict__ maskh,
                     __half* __restrict__ out)
{
    extern __shared__ char smc[];
    uint32_t sb = (uint32_t)__cvta_generic_to_shared(smc);
    const uint32_t sQ = sb + SM_Q * 2;
    const uint32_t sP = sb + SM_P * 2;
    const uint32_t sK0 = sb + SM_K * 2;
    const uint32_t sV0 = sb + SM_V * 2;
    const uint32_t sM0 = sb + SM_M * 2;

    int tid  = threadIdx.x;
    int lane = tid & 31;
    int wid  = tid >> 5;
    int bth  = blockIdx.y;
    int bt   = bth / H_;
    int h    = bth % H_;
    int n0   = blockIdx.x * 128;
    size_t gbase = (size_t)bt * N_ * D_ + (size_t)h * HD_;

    // Q tile via cp.async
    #pragma unroll
    for (int r = 0; r < 4; r++) {
        int e    = tid + r * 256;
        int row  = e >> 3;
        int cseg = e & 7;
        int gn = n0 + row;
        const __half* src = q + gbase + (size_t)(gn < N_ ? gn : 0) * D_ + cseg * 8;
        uint32_t dst = sQ + (row * PB + cseg * 8) * 2;
        int sz = (gn < N_) ? 16 : 0;
        asm volatile("cp.async.ca.shared.global [%0], [%1], 16, %2;"
                     :: "r"(dst), "l"(src), "r"(sz));
    }
    // K/V tile + mask tile loader (one commit group)
    auto load_kvm = [&](int m0, int buf) {
        uint32_t kdst0 = sK0 + buf * 64 * PB * 2;
        uint32_t vdst0 = sV0 + buf * 64 * PB * 2;
        uint32_t mdst0 = sM0 + buf * 128 * PB * 2;
        #pragma unroll
        for (int r = 0; r < 2; r++) {
            int e    = tid + r * 256;
            int row  = e >> 3;
            int cseg = e & 7;
            int gm = m0 + row;
            size_t goff = gbase + (size_t)(gm < N_ ? gm : 0) * D_ + cseg * 8;
            int sz = (gm < N_) ? 16 : 0;
            uint32_t kd = kdst0 + (row * PB + cseg * 8) * 2;
            uint32_t vd = vdst0 + (row * PB + cseg * 8) * 2;
            asm volatile("cp.async.ca.shared.global [%0], [%1], 16, %2;"
                         :: "r"(kd), "l"(k + goff), "r"(sz));
            asm volatile("cp.async.ca.shared.global [%0], [%1], 16, %2;"
                         :: "r"(vd), "l"(v + goff), "r"(sz));
        }
        // mask tile: 128 q-rows x 64 kv-cols (fp16, fully padded in gmem)
        #pragma unroll
        for (int r = 0; r < 4; r++) {
            int e    = tid + r * 256;        // 0..1023
            int row  = e >> 3;               // 0..127
            int cseg = e & 7;
            int gr = n0 + row;
            const __half* src = maskh + (size_t)(gr < N_ ? gr : 0) * MP + m0 + cseg * 8;
            uint32_t md = mdst0 + (row * PB + cseg * 8) * 2;
            asm volatile("cp.async.ca.shared.global [%0], [%1], 16;"
                         :: "r"(md), "l"(src));
        }
        asm volatile("cp.async.commit_group;");
    };

    load_kvm(0, 0);

    float oacc[8][4];
    #pragma unroll
    for (int ni = 0; ni < 8; ni++)
        #pragma unroll
        for (int r = 0; r < 4; r++) oacc[ni][r] = 0.f;
    float rsacc[4] = {0.f, 0.f, 0.f, 0.f};
    const uint32_t ONES = 0x3C003C00u;   // (1.0h, 1.0h)

    int qrow_frag = wid * 16 + (lane >> 2);
    int arow  = wid * 16 + (lane & 15);
    int acol8 = (lane >> 4) * 8;
    int brow  = (lane & 7) + ((lane >> 3) & 1) * 8;
    int bcol8 = (lane >> 4) * 8;
    int l4 = lane & 3;

    int buf = 0;
    for (int it = 0; it < 5; it++) {
        int m0 = it * 64;
        if (it < 4) load_kvm(m0 + 64, buf ^ 1);
        if (it < 4) asm volatile("cp.async.wait_group 1;");
        else        asm volatile("cp.async.wait_group 0;");
        __syncthreads();

        uint32_t sK = sK0 + buf * 64 * PB * 2;
        uint32_t sV = sV0 + buf * 64 * PB * 2;
        uint32_t sM = sM0 + buf * 128 * PB * 2;

        // ---- S = Q @ K^T ----
        float sacc[8][4];
        #pragma unroll
        for (int ni = 0; ni < 8; ni++)
            #pragma unroll
            for (int r = 0; r < 4; r++) sacc[ni][r] = 0.f;
        #pragma unroll
        for (int kk = 0; kk < 4; kk++) {
            uint32_t a[4];
            uint32_t sa = sQ + (arow * PB + kk * 16 + acol8) * 2;
            asm volatile(
                "ldmatrix.sync.aligned.m8n8.x4.shared.b16 {%0,%1,%2,%3}, [%4];"
                : "=r"(a[0]), "=r"(a[1]), "=r"(a[2]), "=r"(a[3]) : "r"(sa));
            uint32_t bfr[4][4];
            #pragma unroll
            for (int t = 0; t < 4; t++) {
                uint32_t sbb = sK + ((t * 16 + brow) * PB + kk * 16 + bcol8) * 2;
                asm volatile(
                    "ldmatrix.sync.aligned.m8n8.x4.shared.b16 {%0,%1,%2,%3}, [%4];"
                    : "=r"(bfr[t][0]), "=r"(bfr[t][1]), "=r"(bfr[t][2]), "=r"(bfr[t][3])
                    : "r"(sbb));
            }
            #pragma unroll
            for (int ni = 0; ni < 8; ni++) {
                uint32_t b0 = bfr[ni >> 1][ni & 1];
                uint32_t b1 = bfr[ni >> 1][(ni & 1) + 2];
                asm volatile(
                    "mma.sync.aligned.m16n8k16.row.col.f32.f16.f16.f32 "
                    "{%0,%1,%2,%3}, {%4,%5,%6,%7}, {%8,%9}, {%0,%1,%2,%3};"
                    : "+f"(sacc[ni][0]), "+f"(sacc[ni][1]),
                      "+f"(sacc[ni][2]), "+f"(sacc[ni][3])
                    : "r"(a[0]), "r"(a[1]), "r"(a[2]), "r"(a[3]),
                      "r"(b0), "r"(b1));
            }
        }

        // ---- P = exp2(s * m') from smem mask; row sums via mma below ----
        #pragma unroll
        for (int u = 0; u < 2; u++) {
            int rloc = qrow_frag + u * 8;
            #pragma unroll
            for (int ni = 0; ni < 8; ni++) {
                int c = ni * 8 + 2 * l4;
                uint32_t mh;
                asm volatile("ld.shared.b32 %0, [%1];"
                             : "=r"(mh) : "r"(sM + (rloc * PB + c) * 2));
                __half2 mh2 = *(__half2*)&mh;
                float2 mv = __half22float2(mh2);
                float e0 = 0.f, e1 = 0.f;
                if (m0 + c     < N_) e0 = ex2f(sacc[ni][2 * u + 0] * mv.x);
                if (m0 + c + 1 < N_) e1 = ex2f(sacc[ni][2 * u + 1] * mv.y);
                uint32_t pk = pack_f16x2(e0, e1);
                asm volatile("st.shared.b32 [%0], %1;"
                             :: "r"(sP + (rloc * PB + c) * 2), "r"(pk));
            }
        }
        __syncwarp();   // P rows are warp-private

        // ---- O += P @ V ; rowsum += P @ ones ----
        #pragma unroll
        for (int kk = 0; kk < 4; kk++) {
            uint32_t a[4];
            uint32_t sa = sP + (arow * PB + kk * 16 + acol8) * 2;
            asm volatile(
                "ldmatrix.sync.aligned.m8n8.x4.shared.b16 {%0,%1,%2,%3}, [%4];"
                : "=r"(a[0]), "=r"(a[1]), "=r"(a[2]), "=r"(a[3]) : "r"(sa));
            // rowsum mma (B = ones; OOB P already zeroed)
            asm volatile(
                "mma.sync.aligned.m16n8k16.row.col.f32.f16.f16.f32 "
                "{%0,%1,%2,%3}, {%4,%5,%6,%7}, {%8,%9}, {%0,%1,%2,%3};"
                : "+f"(rsacc[0]), "+f"(rsacc[1]), "+f"(rsacc[2]), "+f"(rsacc[3])
                : "r"(a[0]), "r"(a[1]), "r"(a[2]), "r"(a[3]),
                  "r"(ONES), "r"(ONES));
            uint32_t bfr[4][4];
            #pragma unroll
            for (int t = 0; t < 4; t++) {
                uint32_t sbb = sV + ((kk * 16 + brow) * PB + t * 16 + bcol8) * 2;
                asm volatile(
                    "ldmatrix.sync.aligned.m8n8.x4.trans.shared.b16 {%0,%1,%2,%3}, [%4];"
                    : "=r"(bfr[t][0]), "=r"(bfr[t][1]), "=r"(bfr[t][2]), "=r"(bfr[t][3])
                    : "r"(sbb));
            }
            #pragma unroll
            for (int ni = 0; ni < 8; ni++) {
                uint32_t b0 = bfr[ni >> 1][(ni & 1) * 2];
                uint32_t b1 = bfr[ni >> 1][(ni & 1) * 2 + 1];
                asm volatile(
                    "mma.sync.aligned.m16n8k16.row.col.f32.f16.f16.f32 "
                    "{%0,%1,%2,%3}, {%4,%5,%6,%7}, {%8,%9}, {%0,%1,%2,%3};"
                    : "+f"(oacc[ni][0]), "+f"(oacc[ni][1]),
                      "+f"(oacc[ni][2]), "+f"(oacc[ni][3])
                    : "r"(a[0]), "r"(a[1]), "r"(a[2]), "r"(a[3]),
                      "r"(b0), "r"(b1));
            }
        }
        __syncthreads();
        buf ^= 1;
    }

    // epilogue: normalize with mma rowsum, store fp16
    #pragma unroll
    for (int u = 0; u < 2; u++) {
        int gr = n0 + qrow_frag + u * 8;
        if (gr >= N_) continue;
        float inv = 1.f / rsacc[2 * u];
        #pragma unroll
        for (int ni = 0; ni < 8; ni++) {
            int dc = ni * 8 + 2 * l4;
            *(uint32_t*)(out + gbase + (size_t)gr * D_ + dc) =
                pack_f16x2(oacc[ni][2 * u] * inv, oacc[ni][2 * u + 1] * inv);
        }
    }
}

// ---------------- launch ----------------
extern "C" void kernel_launch(void* const* d_in, const int* in_sizes, int n_in,
                              void* d_out, int out_size)
{
    const float* query = (const float*)d_in[0];
    const float* key   = (const float*)d_in[1];
    const float* value = (const float*)d_in[2];
    const float* sem   = (const float*)d_in[3];
    const float* Wq    = (const float*)d_in[4];
    const float* bq    = (const float*)d_in[5];
    const float* Wk    = (const float*)d_in[6];
    const float* bk    = (const float*)d_in[7];
    const float* Wv    = (const float*)d_in[8];
    const float* bv    = (const float*)d_in[9];
    const float* Wo    = (const float*)d_in[10];
    const float* bo    = (const float*)d_in[11];
    float* out = (float*)d_out;

    __half *mask_p, *qh_p, *kh_p, *vh_p, *oh_p, *wt_p;
    cudaGetSymbolAddress((void**)&mask_p, g_maskh);
    cudaGetSymbolAddress((void**)&qh_p,   g_qh);
    cudaGetSymbolAddress((void**)&kh_p,   g_kh);
    cudaGetSymbolAddress((void**)&vh_p,   g_vh);
    cudaGetSymbolAddress((void**)&oh_p,   g_oh);
    cudaGetSymbolAddress((void**)&wt_p,   g_wt);

    static bool attr_set = false;
    if (!attr_set) {
        cudaFuncSetAttribute(attn_mma_kernel,
                             cudaFuncAttributeMaxDynamicSharedMemorySize, ATTN_SMEM);
        cudaFuncSetAttribute(gemm_bias_f16_kernel<false, true>,
                             cudaFuncAttributeMaxDynamicSharedMemorySize, GEMM_SMEM);
        cudaFuncSetAttribute(gemm_bias_f16_kernel<true, false>,
                             cudaFuncAttributeMaxDynamicSharedMemorySize, GEMM_SMEM);
        attr_set = true;
    }

    mask_softmax_kernel<<<N_, 256>>>(sem, mask_p);

    dim3 tg(D_ / 32, D_ / 32, 4);
    transpose_w_kernel<<<tg, dim3(32, 8)>>>(Wq, Wk, Wv, Wo, wt_p);

    dim3 g3(D_ / 128, (M_TOT + 127) / 128, 3);
    gemm_bias_f16_kernel<false, true><<<g3, 256, GEMM_SMEM>>>(
        query, key, value, wt_p, bq, bk, bv, qh_p, kh_p, vh_p, M_TOT);

    dim3 ga((N_ + 127) / 128, B_ * T_ * H_);
    attn_mma_kernel<<<ga, 256, ATTN_SMEM>>>(qh_p, kh_p, vh_p, mask_p, oh_p);

    dim3 g1(D_ / 128, (M_TOT + 127) / 128, 1);
    gemm_bias_f16_kernel<true, false><<<g1, 256, GEMM_SMEM>>>(
        oh_p, oh_p, oh_p, wt_p + 3 * (size_t)D_ * D_, bo, bo, bo,
        out, out, out, M_TOT);
}

// round 15
// speedup vs baseline: 1.4117x; 1.1436x over previous
#include <cuda_runtime.h>
#include <cuda_fp16.h>
#include <math.h>
#include <cstdint>

#define B_   8
#define T_   12
#define N_   307
#define D_   512
#define H_   8
#define HD_  64
#define M_TOT (B_*T_*N_)   // 29472
#define MP   320           // padded mask row pitch (halves)

// ---------------- device scratch (allocation-free rule) ----------------
__device__ __half g_maskh[N_*MP];          // fp16 mask, premul by 0.125*log2e
__device__ __half g_qh[M_TOT*D_];
__device__ __half g_kh[M_TOT*D_];
__device__ __half g_vh[M_TOT*D_];
__device__ __half g_oh[M_TOT*D_];
__device__ __half g_wt[4*D_*D_];           // transposed fp16 weights [N][K]

__device__ __forceinline__ uint32_t pack_f16x2(float lo, float hi) {
    uint32_t r;
    asm("cvt.rn.f16x2.f32 %0, %1, %2;" : "=r"(r) : "f"(hi), "f"(lo));
    return r;
}
__device__ __forceinline__ float ex2f(float x) {
    float r;
    asm("ex2.approx.f32 %0, %1;" : "=f"(r) : "f"(x));
    return r;
}

// ---------------- mask = row-softmax * (0.125*log2e) -> fp16 -----------
__global__ void mask_softmax_kernel(const float* __restrict__ sem,
                                    __half* __restrict__ mask)
{
    int row = blockIdx.x;
    int tid = threadIdx.x;
    __shared__ float red[256];
    const float* x = sem + (size_t)row * N_;
    float v0 = (tid       < N_) ? x[tid]       : -INFINITY;
    float v1 = (tid + 256 < N_) ? x[tid + 256] : -INFINITY;
    red[tid] = fmaxf(v0, v1);
    __syncthreads();
    for (int s = 128; s > 0; s >>= 1) {
        if (tid < s) red[tid] = fmaxf(red[tid], red[tid + s]);
        __syncthreads();
    }
    float rowmax = red[0];
    __syncthreads();
    float e0 = (tid       < N_) ? __expf(v0 - rowmax) : 0.f;
    float e1 = (tid + 256 < N_) ? __expf(v1 - rowmax) : 0.f;
    red[tid] = e0 + e1;
    __syncthreads();
    for (int s = 128; s > 0; s >>= 1) {
        if (tid < s) red[tid] += red[tid + s];
        __syncthreads();
    }
    float inv = 0.180336880f / red[0];   // 0.125 * log2(e) / sum
    if (tid       < N_) mask[(size_t)row * MP + tid]       = __float2half(e0 * inv);
    if (tid + 256 < N_) mask[(size_t)row * MP + tid + 256] = __float2half(e1 * inv);
    if (tid == 0)
        for (int c = N_; c < MP; c++) mask[(size_t)row * MP + c] = __float2half(0.f);
}

// ---------------- W -> W^T (fp16), 4 matrices ----------------
__global__ void transpose_w_kernel(const float* __restrict__ w0,
                                   const float* __restrict__ w1,
                                   const float* __restrict__ w2,
                                   const float* __restrict__ w3,
                                   __half* __restrict__ wt)
{
    __shared__ float t[32][33];
    int z  = blockIdx.z;
    const float* src = (z == 0) ? w0 : (z == 1) ? w1 : (z == 2) ? w2 : w3;
    __half* dst = wt + (size_t)z * D_ * D_;
    int tx = threadIdx.x, ty = threadIdx.y;
    int bx = blockIdx.x * 32, by = blockIdx.y * 32;
    #pragma unroll
    for (int i = 0; i < 32; i += 8)
        t[ty + i][tx] = src[(size_t)(by + ty + i) * D_ + bx + tx];
    __syncthreads();
    #pragma unroll
    for (int i = 0; i < 32; i += 8)
        dst[(size_t)(bx + ty + i) * D_ + by + tx] = __float2half(t[tx][ty + i]);
}

// ---------------- fp16 mma GEMM (m16n8k16), frozen ---------------------
#define GP 72
#define TILE_H (128 * GP)
#define GEMM_SMEM (4 * TILE_H * 2)        // 73728 B

template<bool F16_IN, bool F16_OUT>
__global__ __launch_bounds__(256, 2)
void gemm_bias_f16_kernel(const void* __restrict__ A0, const void* __restrict__ A1,
                          const void* __restrict__ A2, const __half* __restrict__ WtB,
                          const float* __restrict__ b0p, const float* __restrict__ b1p,
                          const float* __restrict__ b2p,
                          void* __restrict__ C0, void* __restrict__ C1,
                          void* __restrict__ C2, int M)
{
    extern __shared__ __half gsh[];
    int z = blockIdx.z;
    const void* Av     = (z == 0) ? A0 : (z == 1) ? A1 : A2;
    const __half* Wt   = WtB + (size_t)z * D_ * D_;
    const float* bias  = (z == 0) ? b0p : (z == 1) ? b1p : b2p;
    void* Cv           = (z == 0) ? C0 : (z == 1) ? C1 : C2;

    int tid  = threadIdx.x;
    int lane = tid & 31;
    int wid  = tid >> 5;
    int warp_m = wid & 1;
    int warp_n = wid >> 1;
    int m0 = blockIdx.y * 128;
    int n0 = blockIdx.x * 128;

    float acc[4][4][4];
    #pragma unroll
    for (int mi = 0; mi < 4; mi++)
        #pragma unroll
        for (int ni = 0; ni < 4; ni++)
            #pragma unroll
            for (int r = 0; r < 4; r++) acc[mi][ni][r] = 0.f;

    float4 stA[4][2];

    auto ldg_A = [&](int k0) {
        const float* A = (const float*)Av;
        #pragma unroll
        for (int r = 0; r < 4; r++) {
            int e   = tid + r * 256;
            int row = e >> 3;
            int seg = e & 7;
            int gm = m0 + row;
            if (gm < M) {
                const float* src = A + (size_t)gm * D_ + k0 + seg * 8;
                stA[r][0] = *(const float4*)(src);
                stA[r][1] = *(const float4*)(src + 4);
            } else {
                stA[r][0] = make_float4(0.f, 0.f, 0.f, 0.f);
                stA[r][1] = make_float4(0.f, 0.f, 0.f, 0.f);
            }
        }
    };
    auto sts_A = [&](int b) {
        __half* Ab = gsh + b * 2 * TILE_H;
        #pragma unroll
        for (int r = 0; r < 4; r++) {
            int e   = tid + r * 256;
            int row = e >> 3;
            int seg = e & 7;
            uint4 p;
            p.x = pack_f16x2(stA[r][0].x, stA[r][0].y);
            p.y = pack_f16x2(stA[r][0].z, stA[r][0].w);
            p.z = pack_f16x2(stA[r][1].x, stA[r][1].y);
            p.w = pack_f16x2(stA[r][1].z, stA[r][1].w);
            *(uint4*)(Ab + row * GP + seg * 8) = p;
        }
    };
    auto cpa_A = [&](int b, int k0) {
        const __half* A = (const __half*)Av;
        __half* Ab = gsh + b * 2 * TILE_H;
        #pragma unroll
        for (int r = 0; r < 4; r++) {
            int e   = tid + r * 256;
            int row = e >> 3;
            int seg = e & 7;
            int gm = m0 + row;
            const __half* src = A + (size_t)(gm < M ? gm : 0) * D_ + k0 + seg * 8;
            int sz = (gm < M) ? 16 : 0;
            uint32_t dst = (uint32_t)__cvta_generic_to_shared(Ab + row * GP + seg * 8);
            asm volatile("cp.async.ca.shared.global [%0], [%1], 16, %2;"
                         :: "r"(dst), "l"(src), "r"(sz));
        }
    };
    auto cpa_W = [&](int b, int k0) {
        __half* Wb = gsh + b * 2 * TILE_H + TILE_H;
        #pragma unroll
        for (int r = 0; r < 4; r++) {
            int e   = tid + r * 256;
            int row = e >> 3;
            int seg = e & 7;
            uint32_t dst = (uint32_t)__cvta_generic_to_shared(Wb + row * GP + seg * 8);
            const __half* src = Wt + (size_t)(n0 + row) * D_ + k0 + seg * 8;
            asm volatile("cp.async.ca.shared.global [%0], [%1], 16;"
                         :: "r"(dst), "l"(src));
        }
        asm volatile("cp.async.commit_group;");
    };

    if (F16_IN) { cpa_A(0, 0); cpa_W(0, 0); }
    else        { ldg_A(0); cpa_W(0, 0); sts_A(0); }
    asm volatile("cp.async.wait_group 0;");
    __syncthreads();

    int arow_sub = lane & 15;
    int acol8    = (lane >> 4) * 8;
    int brow_sub = (lane & 7) + ((lane >> 3) & 1) * 8;
    int bcol8    = (lane >> 4) * 8;

    int buf = 0;
    for (int k0 = 0; k0 < D_; k0 += 64) {
        bool last = (k0 == D_ - 64);
        if (!last) {
            if (F16_IN) { cpa_A(buf ^ 1, k0 + 64); cpa_W(buf ^ 1, k0 + 64); }
            else        { ldg_A(k0 + 64); cpa_W(buf ^ 1, k0 + 64); }
        }

        __half* Ab = gsh + buf * 2 * TILE_H;
        __half* Wb = Ab + TILE_H;
        #pragma unroll
        for (int kk = 0; kk < 4; kk++) {
            uint32_t a[4][4];
            #pragma unroll
            for (int mi = 0; mi < 4; mi++) {
                uint32_t sa = (uint32_t)__cvta_generic_to_shared(
                    Ab + (warp_m * 64 + mi * 16 + arow_sub) * GP + kk * 16 + acol8);
                asm volatile(
                    "ldmatrix.sync.aligned.m8n8.x4.shared.b16 {%0,%1,%2,%3}, [%4];"
                    : "=r"(a[mi][0]), "=r"(a[mi][1]), "=r"(a[mi][2]), "=r"(a[mi][3])
                    : "r"(sa));
            }
            uint32_t bfr[2][4];
            #pragma unroll
            for (int t = 0; t < 2; t++) {
                uint32_t sbb = (uint32_t)__cvta_generic_to_shared(
                    Wb + (warp_n * 32 + t * 16 + brow_sub) * GP + kk * 16 + bcol8);
                asm volatile(
                    "ldmatrix.sync.aligned.m8n8.x4.shared.b16 {%0,%1,%2,%3}, [%4];"
                    : "=r"(bfr[t][0]), "=r"(bfr[t][1]), "=r"(bfr[t][2]), "=r"(bfr[t][3])
                    : "r"(sbb));
            }
            #pragma unroll
            for (int ni = 0; ni < 4; ni++) {
                uint32_t b0 = bfr[ni >> 1][ni & 1];
                uint32_t b1 = bfr[ni >> 1][(ni & 1) + 2];
                #pragma unroll
                for (int mi = 0; mi < 4; mi++) {
                    asm volatile(
                        "mma.sync.aligned.m16n8k16.row.col.f32.f16.f16.f32 "
                        "{%0,%1,%2,%3}, {%4,%5,%6,%7}, {%8,%9}, {%0,%1,%2,%3};"
                        : "+f"(acc[mi][ni][0]), "+f"(acc[mi][ni][1]),
                          "+f"(acc[mi][ni][2]), "+f"(acc[mi][ni][3])
                        : "r"(a[mi][0]), "r"(a[mi][1]), "r"(a[mi][2]), "r"(a[mi][3]),
                          "r"(b0), "r"(b1));
                }
            }
        }
        if (!last) {
            if (!F16_IN) sts_A(buf ^ 1);
            asm volatile("cp.async.wait_group 0;");
            __syncthreads();
            buf ^= 1;
        }
    }

    int crow = m0 + warp_m * 64 + (lane >> 2);
    int ccol0 = n0 + warp_n * 32 + 2 * (lane & 3);
    #pragma unroll
    for (int mi = 0; mi < 4; mi++) {
        int r0 = crow + mi * 16;
        #pragma unroll
        for (int ni = 0; ni < 4; ni++) {
            int cc = ccol0 + ni * 8;
            float bb0 = bias[cc], bb1 = bias[cc + 1];
            if (F16_OUT) {
                __half* C = (__half*)Cv;
                if (r0 < M)
                    *(uint32_t*)(C + (size_t)r0 * D_ + cc) =
                        pack_f16x2(acc[mi][ni][0] + bb0, acc[mi][ni][1] + bb1);
                if (r0 + 8 < M)
                    *(uint32_t*)(C + (size_t)(r0 + 8) * D_ + cc) =
                        pack_f16x2(acc[mi][ni][2] + bb0, acc[mi][ni][3] + bb1);
            } else {
                float* C = (float*)Cv;
                if (r0 < M) {
                    float2 o = make_float2(acc[mi][ni][0] + bb0, acc[mi][ni][1] + bb1);
                    *(float2*)(C + (size_t)r0 * D_ + cc) = o;
                }
                if (r0 + 8 < M) {
                    float2 o = make_float2(acc[mi][ni][2] + bb0, acc[mi][ni][3] + bb1);
                    *(float2*)(C + (size_t)(r0 + 8) * D_ + cc) = o;
                }
            }
        }
    }
}

// ---------------- fp16 flash attention: P stays in registers -----------
// QK C-frag maps directly onto PV A-frag: no P smem, no predicates
// (OOB cols give P=1 vs zero V rows; rowsum over-count = exactly 13).
#define PB 72
#define SM_Q  0
#define SM_K  (128 * PB)                     // [2][64*PB]
#define SM_V  (SM_K + 2 * 64 * PB)           // [2][64*PB]
#define SM_M  (SM_V + 2 * 64 * PB)           // [2][128*PB]
#define ATTN_SMEM ((SM_M + 2 * 128 * PB) * 2)   // 92160 B

__global__ __launch_bounds__(256, 2)
void attn_mma_kernel(const __half* __restrict__ q,
                     const __half* __restrict__ k,
                     const __half* __restrict__ v,
                     const __half* __restrict__ maskh,
                     __half* __restrict__ out)
{
    extern __shared__ char smc[];
    uint32_t sb = (uint32_t)__cvta_generic_to_shared(smc);
    const uint32_t sQ = sb + SM_Q * 2;
    const uint32_t sK0 = sb + SM_K * 2;
    const uint32_t sV0 = sb + SM_V * 2;
    const uint32_t sM0 = sb + SM_M * 2;

    int tid  = threadIdx.x;
    int lane = tid & 31;
    int wid  = tid >> 5;
    int bth  = blockIdx.y;
    int bt   = bth / H_;
    int h    = bth % H_;
    int n0   = blockIdx.x * 128;
    size_t gbase = (size_t)bt * N_ * D_ + (size_t)h * HD_;

    // Q tile via cp.async
    #pragma unroll
    for (int r = 0; r < 4; r++) {
        int e    = tid + r * 256;
        int row  = e >> 3;
        int cseg = e & 7;
        int gn = n0 + row;
        const __half* src = q + gbase + (size_t)(gn < N_ ? gn : 0) * D_ + cseg * 8;
        uint32_t dst = sQ + (row * PB + cseg * 8) * 2;
        int sz = (gn < N_) ? 16 : 0;
        asm volatile("cp.async.ca.shared.global [%0], [%1], 16, %2;"
                     :: "r"(dst), "l"(src), "r"(sz));
    }
    // K/V + mask tiles, one commit group
    auto load_kvm = [&](int m0, int buf) {
        uint32_t kdst0 = sK0 + buf * 64 * PB * 2;
        uint32_t vdst0 = sV0 + buf * 64 * PB * 2;
        uint32_t mdst0 = sM0 + buf * 128 * PB * 2;
        #pragma unroll
        for (int r = 0; r < 2; r++) {
            int e    = tid + r * 256;
            int row  = e >> 3;
            int cseg = e & 7;
            int gm = m0 + row;
            size_t goff = gbase + (size_t)(gm < N_ ? gm : 0) * D_ + cseg * 8;
            int sz = (gm < N_) ? 16 : 0;
            uint32_t kd = kdst0 + (row * PB + cseg * 8) * 2;
            uint32_t vd = vdst0 + (row * PB + cseg * 8) * 2;
            asm volatile("cp.async.ca.shared.global [%0], [%1], 16, %2;"
                         :: "r"(kd), "l"(k + goff), "r"(sz));
            asm volatile("cp.async.ca.shared.global [%0], [%1], 16, %2;"
                         :: "r"(vd), "l"(v + goff), "r"(sz));
        }
        #pragma unroll
        for (int r = 0; r < 4; r++) {
            int e    = tid + r * 256;
            int row  = e >> 3;
            int cseg = e & 7;
            int gr = n0 + row;
            const __half* src = maskh + (size_t)(gr < N_ ? gr : 0) * MP + m0 + cseg * 8;
            uint32_t md = mdst0 + (row * PB + cseg * 8) * 2;
            asm volatile("cp.async.ca.shared.global [%0], [%1], 16;"
                         :: "r"(md), "l"(src));
        }
        asm volatile("cp.async.commit_group;");
    };

    load_kvm(0, 0);

    float oacc[8][4];
    #pragma unroll
    for (int ni = 0; ni < 8; ni++)
        #pragma unroll
        for (int r = 0; r < 4; r++) oacc[ni][r] = 0.f;
    float rsacc[4] = {0.f, 0.f, 0.f, 0.f};
    const uint32_t ONES = 0x3C003C00u;   // (1.0h, 1.0h)

    int qrow_frag = wid * 16 + (lane >> 2);   // row r (and r+8)
    int arow  = wid * 16 + (lane & 15);
    int acol8 = (lane >> 4) * 8;
    int brow  = (lane & 7) + ((lane >> 3) & 1) * 8;
    int bcol8 = (lane >> 4) * 8;
    int l4 = lane & 3;

    int buf = 0;
    for (int it = 0; it < 5; it++) {
        int m0 = it * 64;
        if (it < 4) load_kvm(m0 + 64, buf ^ 1);
        if (it < 4) asm volatile("cp.async.wait_group 1;");
        else        asm volatile("cp.async.wait_group 0;");
        __syncthreads();

        uint32_t sK = sK0 + buf * 64 * PB * 2;
        uint32_t sV = sV0 + buf * 64 * PB * 2;
        uint32_t sM = sM0 + buf * 128 * PB * 2;

        // ---- S = Q @ K^T ----
        float sacc[8][4];
        #pragma unroll
        for (int ni = 0; ni < 8; ni++)
            #pragma unroll
            for (int r = 0; r < 4; r++) sacc[ni][r] = 0.f;
        #pragma unroll
        for (int kk = 0; kk < 4; kk++) {
            uint32_t a[4];
            uint32_t sa = sQ + (arow * PB + kk * 16 + acol8) * 2;
            asm volatile(
                "ldmatrix.sync.aligned.m8n8.x4.shared.b16 {%0,%1,%2,%3}, [%4];"
                : "=r"(a[0]), "=r"(a[1]), "=r"(a[2]), "=r"(a[3]) : "r"(sa));
            uint32_t bfr[4][4];
            #pragma unroll
            for (int t = 0; t < 4; t++) {
                uint32_t sbb = sK + ((t * 16 + brow) * PB + kk * 16 + bcol8) * 2;
                asm volatile(
                    "ldmatrix.sync.aligned.m8n8.x4.shared.b16 {%0,%1,%2,%3}, [%4];"
                    : "=r"(bfr[t][0]), "=r"(bfr[t][1]), "=r"(bfr[t][2]), "=r"(bfr[t][3])
                    : "r"(sbb));
            }
            #pragma unroll
            for (int ni = 0; ni < 8; ni++) {
                uint32_t b0 = bfr[ni >> 1][ni & 1];
                uint32_t b1 = bfr[ni >> 1][(ni & 1) + 2];
                asm volatile(
                    "mma.sync.aligned.m16n8k16.row.col.f32.f16.f16.f32 "
                    "{%0,%1,%2,%3}, {%4,%5,%6,%7}, {%8,%9}, {%0,%1,%2,%3};"
                    : "+f"(sacc[ni][0]), "+f"(sacc[ni][1]),
                      "+f"(sacc[ni][2]), "+f"(sacc[ni][3])
                    : "r"(a[0]), "r"(a[1]), "r"(a[2]), "r"(a[3]),
                      "r"(b0), "r"(b1));
            }
        }

        // ---- softmax in regs + P@V + rowsum, per k-chunk ----
        #pragma unroll
        for (int kk = 0; kk < 4; kk++) {
            // build P A-fragment from sacc[2kk], sacc[2kk+1]
            uint32_t pa[4];
            #pragma unroll
            for (int j = 0; j < 2; j++) {
                int ni = 2 * kk + j;
                int c  = ni * 8 + 2 * l4;
                uint32_t mh0, mh1;
                asm volatile("ld.shared.b32 %0, [%1];"
                             : "=r"(mh0) : "r"(sM + (qrow_frag * PB + c) * 2));
                asm volatile("ld.shared.b32 %0, [%1];"
                             : "=r"(mh1) : "r"(sM + ((qrow_frag + 8) * PB + c) * 2));
                float2 m0v = __half22float2(*(__half2*)&mh0);
                float2 m1v = __half22float2(*(__half2*)&mh1);
                float e0 = ex2f(sacc[ni][0] * m0v.x);
                float e1 = ex2f(sacc[ni][1] * m0v.y);
                float e2 = ex2f(sacc[ni][2] * m1v.x);
                float e3 = ex2f(sacc[ni][3] * m1v.y);
                pa[2 * j]     = pack_f16x2(e0, e1);
                pa[2 * j + 1] = pack_f16x2(e2, e3);
            }
            // rowsum += P @ ones
            asm volatile(
                "mma.sync.aligned.m16n8k16.row.col.f32.f16.f16.f32 "
                "{%0,%1,%2,%3}, {%4,%5,%6,%7}, {%8,%9}, {%0,%1,%2,%3};"
                : "+f"(rsacc[0]), "+f"(rsacc[1]), "+f"(rsacc[2]), "+f"(rsacc[3])
                : "r"(pa[0]), "r"(pa[1]), "r"(pa[2]), "r"(pa[3]),
                  "r"(ONES), "r"(ONES));
            // O += P @ V
            uint32_t bfr[4][4];
            #pragma unroll
            for (int t = 0; t < 4; t++) {
                uint32_t sbb = sV + ((kk * 16 + brow) * PB + t * 16 + bcol8) * 2;
                asm volatile(
                    "ldmatrix.sync.aligned.m8n8.x4.trans.shared.b16 {%0,%1,%2,%3}, [%4];"
                    : "=r"(bfr[t][0]), "=r"(bfr[t][1]), "=r"(bfr[t][2]), "=r"(bfr[t][3])
                    : "r"(sbb));
            }
            #pragma unroll
            for (int ni = 0; ni < 8; ni++) {
                uint32_t b0 = bfr[ni >> 1][(ni & 1) * 2];
                uint32_t b1 = bfr[ni >> 1][(ni & 1) * 2 + 1];
                asm volatile(
                    "mma.sync.aligned.m16n8k16.row.col.f32.f16.f16.f32 "
                    "{%0,%1,%2,%3}, {%4,%5,%6,%7}, {%8,%9}, {%0,%1,%2,%3};"
                    : "+f"(oacc[ni][0]), "+f"(oacc[ni][1]),
                      "+f"(oacc[ni][2]), "+f"(oacc[ni][3])
                    : "r"(pa[0]), "r"(pa[1]), "r"(pa[2]), "r"(pa[3]),
                      "r"(b0), "r"(b1));
            }
        }
        __syncthreads();
        buf ^= 1;
    }

    // epilogue: subtract OOB rowsum overcount (exactly 320-307=13), store
    #pragma unroll
    for (int u = 0; u < 2; u++) {
        int gr = n0 + qrow_frag + u * 8;
        if (gr >= N_) continue;
        float inv = 1.f / (rsacc[2 * u] - 13.0f);
        #pragma unroll
        for (int ni = 0; ni < 8; ni++) {
            int dc = ni * 8 + 2 * l4;
            *(uint32_t*)(out + gbase + (size_t)gr * D_ + dc) =
                pack_f16x2(oacc[ni][2 * u] * inv, oacc[ni][2 * u + 1] * inv);
        }
    }
}

// ---------------- launch ----------------
extern "C" void kernel_launch(void* const* d_in, const int* in_sizes, int n_in,
                              void* d_out, int out_size)
{
    const float* query = (const float*)d_in[0];
    const float* key   = (const float*)d_in[1];
    const float* value = (const float*)d_in[2];
    const float* sem   = (const float*)d_in[3];
    const float* Wq    = (const float*)d_in[4];
    const float* bq    = (const float*)d_in[5];
    const float* Wk    = (const float*)d_in[6];
    const float* bk    = (const float*)d_in[7];
    const float* Wv    = (const float*)d_in[8];
    const float* bv    = (const float*)d_in[9];
    const float* Wo    = (const float*)d_in[10];
    const float* bo    = (const float*)d_in[11];
    float* out = (float*)d_out;

    __half *mask_p, *qh_p, *kh_p, *vh_p, *oh_p, *wt_p;
    cudaGetSymbolAddress((void**)&mask_p, g_maskh);
    cudaGetSymbolAddress((void**)&qh_p,   g_qh);
    cudaGetSymbolAddress((void**)&kh_p,   g_kh);
    cudaGetSymbolAddress((void**)&vh_p,   g_vh);
    cudaGetSymbolAddress((void**)&oh_p,   g_oh);
    cudaGetSymbolAddress((void**)&wt_p,   g_wt);

    static bool attr_set = false;
    if (!attr_set) {
        cudaFuncSetAttribute(attn_mma_kernel,
                             cudaFuncAttributeMaxDynamicSharedMemorySize, ATTN_SMEM);
        cudaFuncSetAttribute(gemm_bias_f16_kernel<false, true>,
                             cudaFuncAttributeMaxDynamicSharedMemorySize, GEMM_SMEM);
        cudaFuncSetAttribute(gemm_bias_f16_kernel<true, false>,
                             cudaFuncAttributeMaxDynamicSharedMemorySize, GEMM_SMEM);
        attr_set = true;
    }

    mask_softmax_kernel<<<N_, 256>>>(sem, mask_p);

    dim3 tg(D_ / 32, D_ / 32, 4);
    transpose_w_kernel<<<tg, dim3(32, 8)>>>(Wq, Wk, Wv, Wo, wt_p);

    dim3 g3(D_ / 128, (M_TOT + 127) / 128, 3);
    gemm_bias_f16_kernel<false, true><<<g3, 256, GEMM_SMEM>>>(
        query, key, value, wt_p, bq, bk, bv, qh_p, kh_p, vh_p, M_TOT);

    dim3 ga((N_ + 127) / 128, B_ * T_ * H_);
    attn_mma_kernel<<<ga, 256, ATTN_SMEM>>>(qh_p, kh_p, vh_p, mask_p, oh_p);

    dim3 g1(D_ / 128, (M_TOT + 127) / 128, 1);
    gemm_bias_f16_kernel<true, false><<<g1, 256, GEMM_SMEM>>>(
        oh_p, oh_p, oh_p, wt_p + 3 * (size_t)D_ * D_, bo, bo, bo,
        out, out, out, M_TOT);
}

// round 16
// speedup vs baseline: 1.4577x; 1.0325x over previous
#include <cuda_runtime.h>
#include <cuda_fp16.h>
#include <math.h>
#include <cstdint>

#define B_   8
#define T_   12
#define N_   307
#define D_   512
#define H_   8
#define HD_  64
#define M_TOT (B_*T_*N_)   // 29472
#define MP   320           // padded mask row pitch (halves)

// ---------------- device scratch (allocation-free rule) ----------------
__device__ __half g_maskh[N_*MP];          // fp16 mask, premul by 0.125*log2e
__device__ __half g_qh[M_TOT*D_];
__device__ __half g_kh[M_TOT*D_];
__device__ __half g_vh[M_TOT*D_];
__device__ __half g_oh[M_TOT*D_];
__device__ __half g_wt[4*D_*D_];           // transposed fp16 weights [N][K]

__device__ __forceinline__ uint32_t pack_f16x2(float lo, float hi) {
    uint32_t r;
    asm("cvt.rn.f16x2.f32 %0, %1, %2;" : "=r"(r) : "f"(hi), "f"(lo));
    return r;
}

// ---------------- mask = row-softmax * (0.125*log2e) -> fp16 -----------
__global__ void mask_softmax_kernel(const float* __restrict__ sem,
                                    __half* __restrict__ mask)
{
    int row = blockIdx.x;
    int tid = threadIdx.x;
    __shared__ float red[256];
    const float* x = sem + (size_t)row * N_;
    float v0 = (tid       < N_) ? x[tid]       : -INFINITY;
    float v1 = (tid + 256 < N_) ? x[tid + 256] : -INFINITY;
    red[tid] = fmaxf(v0, v1);
    __syncthreads();
    for (int s = 128; s > 0; s >>= 1) {
        if (tid < s) red[tid] = fmaxf(red[tid], red[tid + s]);
        __syncthreads();
    }
    float rowmax = red[0];
    __syncthreads();
    float e0 = (tid       < N_) ? __expf(v0 - rowmax) : 0.f;
    float e1 = (tid + 256 < N_) ? __expf(v1 - rowmax) : 0.f;
    red[tid] = e0 + e1;
    __syncthreads();
    for (int s = 128; s > 0; s >>= 1) {
        if (tid < s) red[tid] += red[tid + s];
        __syncthreads();
    }
    float inv = 0.180336880f / red[0];   // 0.125 * log2(e) / sum
    if (tid       < N_) mask[(size_t)row * MP + tid]       = __float2half(e0 * inv);
    if (tid + 256 < N_) mask[(size_t)row * MP + tid + 256] = __float2half(e1 * inv);
    if (tid == 0)
        for (int c = N_; c < MP; c++) mask[(size_t)row * MP + c] = __float2half(0.f);
}

// ---------------- W -> W^T (fp16), 4 matrices ----------------
__global__ void transpose_w_kernel(const float* __restrict__ w0,
                                   const float* __restrict__ w1,
                                   const float* __restrict__ w2,
                                   const float* __restrict__ w3,
                                   __half* __restrict__ wt)
{
    __shared__ float t[32][33];
    int z  = blockIdx.z;
    const float* src = (z == 0) ? w0 : (z == 1) ? w1 : (z == 2) ? w2 : w3;
    __half* dst = wt + (size_t)z * D_ * D_;
    int tx = threadIdx.x, ty = threadIdx.y;
    int bx = blockIdx.x * 32, by = blockIdx.y * 32;
    #pragma unroll
    for (int i = 0; i < 32; i += 8)
        t[ty + i][tx] = src[(size_t)(by + ty + i) * D_ + bx + tx];
    __syncthreads();
    #pragma unroll
    for (int i = 0; i < 32; i += 8)
        dst[(size_t)(bx + ty + i) * D_ + by + tx] = __float2half(t[tx][ty + i]);
}

// ---------------- fp16 mma GEMM (m16n8k16), frozen ---------------------
#define GP 72
#define TILE_H (128 * GP)
#define GEMM_SMEM (4 * TILE_H * 2)        // 73728 B

template<bool F16_IN, bool F16_OUT>
__global__ __launch_bounds__(256, 2)
void gemm_bias_f16_kernel(const void* __restrict__ A0, const void* __restrict__ A1,
                          const void* __restrict__ A2, const __half* __restrict__ WtB,
                          const float* __restrict__ b0p, const float* __restrict__ b1p,
                          const float* __restrict__ b2p,
                          void* __restrict__ C0, void* __restrict__ C1,
                          void* __restrict__ C2, int M)
{
    extern __shared__ __half gsh[];
    int z = blockIdx.z;
    const void* Av     = (z == 0) ? A0 : (z == 1) ? A1 : A2;
    const __half* Wt   = WtB + (size_t)z * D_ * D_;
    const float* bias  = (z == 0) ? b0p : (z == 1) ? b1p : b2p;
    void* Cv           = (z == 0) ? C0 : (z == 1) ? C1 : C2;

    int tid  = threadIdx.x;
    int lane = tid & 31;
    int wid  = tid >> 5;
    int warp_m = wid & 1;
    int warp_n = wid >> 1;
    int m0 = blockIdx.y * 128;
    int n0 = blockIdx.x * 128;

    float acc[4][4][4];
    #pragma unroll
    for (int mi = 0; mi < 4; mi++)
        #pragma unroll
        for (int ni = 0; ni < 4; ni++)
            #pragma unroll
            for (int r = 0; r < 4; r++) acc[mi][ni][r] = 0.f;

    float4 stA[4][2];

    auto ldg_A = [&](int k0) {
        const float* A = (const float*)Av;
        #pragma unroll
        for (int r = 0; r < 4; r++) {
            int e   = tid + r * 256;
            int row = e >> 3;
            int seg = e & 7;
            int gm = m0 + row;
            if (gm < M) {
                const float* src = A + (size_t)gm * D_ + k0 + seg * 8;
                stA[r][0] = *(const float4*)(src);
                stA[r][1] = *(const float4*)(src + 4);
            } else {
                stA[r][0] = make_float4(0.f, 0.f, 0.f, 0.f);
                stA[r][1] = make_float4(0.f, 0.f, 0.f, 0.f);
            }
        }
    };
    auto sts_A = [&](int b) {
        __half* Ab = gsh + b * 2 * TILE_H;
        #pragma unroll
        for (int r = 0; r < 4; r++) {
            int e   = tid + r * 256;
            int row = e >> 3;
            int seg = e & 7;
            uint4 p;
            p.x = pack_f16x2(stA[r][0].x, stA[r][0].y);
            p.y = pack_f16x2(stA[r][0].z, stA[r][0].w);
            p.z = pack_f16x2(stA[r][1].x, stA[r][1].y);
            p.w = pack_f16x2(stA[r][1].z, stA[r][1].w);
            *(uint4*)(Ab + row * GP + seg * 8) = p;
        }
    };
    auto cpa_A = [&](int b, int k0) {
        const __half* A = (const __half*)Av;
        __half* Ab = gsh + b * 2 * TILE_H;
        #pragma unroll
        for (int r = 0; r < 4; r++) {
            int e   = tid + r * 256;
            int row = e >> 3;
            int seg = e & 7;
            int gm = m0 + row;
            const __half* src = A + (size_t)(gm < M ? gm : 0) * D_ + k0 + seg * 8;
            int sz = (gm < M) ? 16 : 0;
            uint32_t dst = (uint32_t)__cvta_generic_to_shared(Ab + row * GP + seg * 8);
            asm volatile("cp.async.ca.shared.global [%0], [%1], 16, %2;"
                         :: "r"(dst), "l"(src), "r"(sz));
        }
    };
    auto cpa_W = [&](int b, int k0) {
        __half* Wb = gsh + b * 2 * TILE_H + TILE_H;
        #pragma unroll
        for (int r = 0; r < 4; r++) {
            int e   = tid + r * 256;
            int row = e >> 3;
            int seg = e & 7;
            uint32_t dst = (uint32_t)__cvta_generic_to_shared(Wb + row * GP + seg * 8);
            const __half* src = Wt + (size_t)(n0 + row) * D_ + k0 + seg * 8;
            asm volatile("cp.async.ca.shared.global [%0], [%1], 16;"
                         :: "r"(dst), "l"(src));
        }
        asm volatile("cp.async.commit_group;");
    };

    if (F16_IN) { cpa_A(0, 0); cpa_W(0, 0); }
    else        { ldg_A(0); cpa_W(0, 0); sts_A(0); }
    asm volatile("cp.async.wait_group 0;");
    __syncthreads();

    int arow_sub = lane & 15;
    int acol8    = (lane >> 4) * 8;
    int brow_sub = (lane & 7) + ((lane >> 3) & 1) * 8;
    int bcol8    = (lane >> 4) * 8;

    int buf = 0;
    for (int k0 = 0; k0 < D_; k0 += 64) {
        bool last = (k0 == D_ - 64);
        if (!last) {
            if (F16_IN) { cpa_A(buf ^ 1, k0 + 64); cpa_W(buf ^ 1, k0 + 64); }
            else        { ldg_A(k0 + 64); cpa_W(buf ^ 1, k0 + 64); }
        }

        __half* Ab = gsh + buf * 2 * TILE_H;
        __half* Wb = Ab + TILE_H;
        #pragma unroll
        for (int kk = 0; kk < 4; kk++) {
            uint32_t a[4][4];
            #pragma unroll
            for (int mi = 0; mi < 4; mi++) {
                uint32_t sa = (uint32_t)__cvta_generic_to_shared(
                    Ab + (warp_m * 64 + mi * 16 + arow_sub) * GP + kk * 16 + acol8);
                asm volatile(
                    "ldmatrix.sync.aligned.m8n8.x4.shared.b16 {%0,%1,%2,%3}, [%4];"
                    : "=r"(a[mi][0]), "=r"(a[mi][1]), "=r"(a[mi][2]), "=r"(a[mi][3])
                    : "r"(sa));
            }
            uint32_t bfr[2][4];
            #pragma unroll
            for (int t = 0; t < 2; t++) {
                uint32_t sbb = (uint32_t)__cvta_generic_to_shared(
                    Wb + (warp_n * 32 + t * 16 + brow_sub) * GP + kk * 16 + bcol8);
                asm volatile(
                    "ldmatrix.sync.aligned.m8n8.x4.shared.b16 {%0,%1,%2,%3}, [%4];"
                    : "=r"(bfr[t][0]), "=r"(bfr[t][1]), "=r"(bfr[t][2]), "=r"(bfr[t][3])
                    : "r"(sbb));
            }
            #pragma unroll
            for (int ni = 0; ni < 4; ni++) {
                uint32_t b0 = bfr[ni >> 1][ni & 1];
                uint32_t b1 = bfr[ni >> 1][(ni & 1) + 2];
                #pragma unroll
                for (int mi = 0; mi < 4; mi++) {
                    asm volatile(
                        "mma.sync.aligned.m16n8k16.row.col.f32.f16.f16.f32 "
                        "{%0,%1,%2,%3}, {%4,%5,%6,%7}, {%8,%9}, {%0,%1,%2,%3};"
                        : "+f"(acc[mi][ni][0]), "+f"(acc[mi][ni][1]),
                          "+f"(acc[mi][ni][2]), "+f"(acc[mi][ni][3])
                        : "r"(a[mi][0]), "r"(a[mi][1]), "r"(a[mi][2]), "r"(a[mi][3]),
                          "r"(b0), "r"(b1));
                }
            }
        }
        if (!last) {
            if (!F16_IN) sts_A(buf ^ 1);
            asm volatile("cp.async.wait_group 0;");
            __syncthreads();
            buf ^= 1;
        }
    }

    int crow = m0 + warp_m * 64 + (lane >> 2);
    int ccol0 = n0 + warp_n * 32 + 2 * (lane & 3);
    #pragma unroll
    for (int mi = 0; mi < 4; mi++) {
        int r0 = crow + mi * 16;
        #pragma unroll
        for (int ni = 0; ni < 4; ni++) {
            int cc = ccol0 + ni * 8;
            float bb0 = bias[cc], bb1 = bias[cc + 1];
            if (F16_OUT) {
                __half* C = (__half*)Cv;
                if (r0 < M)
                    *(uint32_t*)(C + (size_t)r0 * D_ + cc) =
                        pack_f16x2(acc[mi][ni][0] + bb0, acc[mi][ni][1] + bb1);
                if (r0 + 8 < M)
                    *(uint32_t*)(C + (size_t)(r0 + 8) * D_ + cc) =
                        pack_f16x2(acc[mi][ni][2] + bb0, acc[mi][ni][3] + bb1);
            } else {
                float* C = (float*)Cv;
                if (r0 < M) {
                    float2 o = make_float2(acc[mi][ni][0] + bb0, acc[mi][ni][1] + bb1);
                    *(float2*)(C + (size_t)r0 * D_ + cc) = o;
                }
                if (r0 + 8 < M) {
                    float2 o = make_float2(acc[mi][ni][2] + bb0, acc[mi][ni][3] + bb1);
                    *(float2*)(C + (size_t)(r0 + 8) * D_ + cc) = o;
                }
            }
        }
    }
}

// ---------------- fp16 flash attention: reg-P + f16x2 softmax ----------
// warp-level skip for fully-OOB q-row bands (tile 3 covers rows 256..383).
#define PB 72
#define SM_Q  0
#define SM_K  (128 * PB)                     // [2][64*PB]
#define SM_V  (SM_K + 2 * 64 * PB)           // [2][64*PB]
#define SM_M  (SM_V + 2 * 64 * PB)           // [2][128*PB]
#define ATTN_SMEM ((SM_M + 2 * 128 * PB) * 2)   // 92160 B

__global__ __launch_bounds__(256, 2)
void attn_mma_kernel(const __half* __restrict__ q,
                     const __half* __restrict__ k,
                     const __half* __restrict__ v,
                     const __half* __restrict__ maskh,
                     __half* __restrict__ out)
{
    extern __shared__ char smc[];
    uint32_t sb = (uint32_t)__cvta_generic_to_shared(smc);
    const uint32_t sQ = sb + SM_Q * 2;
    const uint32_t sK0 = sb + SM_K * 2;
    const uint32_t sV0 = sb + SM_V * 2;
    const uint32_t sM0 = sb + SM_M * 2;

    int tid  = threadIdx.x;
    int lane = tid & 31;
    int wid  = tid >> 5;
    int bth  = blockIdx.y;
    int bt   = bth / H_;
    int h    = bth % H_;
    int n0   = blockIdx.x * 128;
    size_t gbase = (size_t)bt * N_ * D_ + (size_t)h * HD_;
    bool wactive = (n0 + wid * 16) < N_;   // warp has >=1 valid q row

    // Q tile via cp.async
    #pragma unroll
    for (int r = 0; r < 4; r++) {
        int e    = tid + r * 256;
        int row  = e >> 3;
        int cseg = e & 7;
        int gn = n0 + row;
        const __half* src = q + gbase + (size_t)(gn < N_ ? gn : 0) * D_ + cseg * 8;
        uint32_t dst = sQ + (row * PB + cseg * 8) * 2;
        int sz = (gn < N_) ? 16 : 0;
        asm volatile("cp.async.ca.shared.global [%0], [%1], 16, %2;"
                     :: "r"(dst), "l"(src), "r"(sz));
    }
    // K/V + mask tiles, one commit group
    auto load_kvm = [&](int m0, int buf) {
        uint32_t kdst0 = sK0 + buf * 64 * PB * 2;
        uint32_t vdst0 = sV0 + buf * 64 * PB * 2;
        uint32_t mdst0 = sM0 + buf * 128 * PB * 2;
        #pragma unroll
        for (int r = 0; r < 2; r++) {
            int e    = tid + r * 256;
            int row  = e >> 3;
            int cseg = e & 7;
            int gm = m0 + row;
            size_t goff = gbase + (size_t)(gm < N_ ? gm : 0) * D_ + cseg * 8;
            int sz = (gm < N_) ? 16 : 0;
            uint32_t kd = kdst0 + (row * PB + cseg * 8) * 2;
            uint32_t vd = vdst0 + (row * PB + cseg * 8) * 2;
            asm volatile("cp.async.ca.shared.global [%0], [%1], 16, %2;"
                         :: "r"(kd), "l"(k + goff), "r"(sz));
            asm volatile("cp.async.ca.shared.global [%0], [%1], 16, %2;"
                         :: "r"(vd), "l"(v + goff), "r"(sz));
        }
        #pragma unroll
        for (int r = 0; r < 4; r++) {
            int e    = tid + r * 256;
            int row  = e >> 3;
            int cseg = e & 7;
            int gr = n0 + row;
            const __half* src = maskh + (size_t)(gr < N_ ? gr : 0) * MP + m0 + cseg * 8;
            uint32_t md = mdst0 + (row * PB + cseg * 8) * 2;
            asm volatile("cp.async.ca.shared.global [%0], [%1], 16;"
                         :: "r"(md), "l"(src));
        }
        asm volatile("cp.async.commit_group;");
    };

    load_kvm(0, 0);

    float oacc[8][4];
    #pragma unroll
    for (int ni = 0; ni < 8; ni++)
        #pragma unroll
        for (int r = 0; r < 4; r++) oacc[ni][r] = 0.f;
    float rsacc[4] = {0.f, 0.f, 0.f, 0.f};
    const uint32_t ONES = 0x3C003C00u;   // (1.0h, 1.0h)

    int qrow_frag = wid * 16 + (lane >> 2);   // row r (and r+8)
    int arow  = wid * 16 + (lane & 15);
    int acol8 = (lane >> 4) * 8;
    int brow  = (lane & 7) + ((lane >> 3) & 1) * 8;
    int bcol8 = (lane >> 4) * 8;
    int l4 = lane & 3;

    int buf = 0;
    for (int it = 0; it < 5; it++) {
        int m0 = it * 64;
        if (it < 4) load_kvm(m0 + 64, buf ^ 1);
        if (it < 4) asm volatile("cp.async.wait_group 1;");
        else        asm volatile("cp.async.wait_group 0;");
        __syncthreads();

        if (wactive) {
            uint32_t sK = sK0 + buf * 64 * PB * 2;
            uint32_t sV = sV0 + buf * 64 * PB * 2;
            uint32_t sM = sM0 + buf * 128 * PB * 2;

            // ---- S = Q @ K^T ----
            float sacc[8][4];
            #pragma unroll
            for (int ni = 0; ni < 8; ni++)
                #pragma unroll
                for (int r = 0; r < 4; r++) sacc[ni][r] = 0.f;
            #pragma unroll
            for (int kk = 0; kk < 4; kk++) {
                uint32_t a[4];
                uint32_t sa = sQ + (arow * PB + kk * 16 + acol8) * 2;
                asm volatile(
                    "ldmatrix.sync.aligned.m8n8.x4.shared.b16 {%0,%1,%2,%3}, [%4];"
                    : "=r"(a[0]), "=r"(a[1]), "=r"(a[2]), "=r"(a[3]) : "r"(sa));
                uint32_t bfr[4][4];
                #pragma unroll
                for (int t = 0; t < 4; t++) {
                    uint32_t sbb = sK + ((t * 16 + brow) * PB + kk * 16 + bcol8) * 2;
                    asm volatile(
                        "ldmatrix.sync.aligned.m8n8.x4.shared.b16 {%0,%1,%2,%3}, [%4];"
                        : "=r"(bfr[t][0]), "=r"(bfr[t][1]), "=r"(bfr[t][2]), "=r"(bfr[t][3])
                        : "r"(sbb));
                }
                #pragma unroll
                for (int ni = 0; ni < 8; ni++) {
                    uint32_t b0 = bfr[ni >> 1][ni & 1];
                    uint32_t b1 = bfr[ni >> 1][(ni & 1) + 2];
                    asm volatile(
                        "mma.sync.aligned.m16n8k16.row.col.f32.f16.f16.f32 "
                        "{%0,%1,%2,%3}, {%4,%5,%6,%7}, {%8,%9}, {%0,%1,%2,%3};"
                        : "+f"(sacc[ni][0]), "+f"(sacc[ni][1]),
                          "+f"(sacc[ni][2]), "+f"(sacc[ni][3])
                        : "r"(a[0]), "r"(a[1]), "r"(a[2]), "r"(a[3]),
                          "r"(b0), "r"(b1));
                }
            }

            // ---- softmax in f16x2 + P@V + rowsum, per k-chunk ----
            #pragma unroll
            for (int kk = 0; kk < 4; kk++) {
                uint32_t pa[4];
                #pragma unroll
                for (int j = 0; j < 2; j++) {
                    int ni = 2 * kk + j;
                    int c  = ni * 8 + 2 * l4;
                    uint32_t mh0, mh1;
                    asm volatile("ld.shared.b32 %0, [%1];"
                                 : "=r"(mh0) : "r"(sM + (qrow_frag * PB + c) * 2));
                    asm volatile("ld.shared.b32 %0, [%1];"
                                 : "=r"(mh1) : "r"(sM + ((qrow_frag + 8) * PB + c) * 2));
                    uint32_t s01 = pack_f16x2(sacc[ni][0], sacc[ni][1]);
                    uint32_t s23 = pack_f16x2(sacc[ni][2], sacc[ni][3]);
                    uint32_t x01, x23;
                    asm("mul.rn.f16x2 %0, %1, %2;" : "=r"(x01) : "r"(s01), "r"(mh0));
                    asm("mul.rn.f16x2 %0, %1, %2;" : "=r"(x23) : "r"(s23), "r"(mh1));
                    asm("ex2.approx.f16x2 %0, %1;" : "=r"(pa[2 * j])     : "r"(x01));
                    asm("ex2.approx.f16x2 %0, %1;" : "=r"(pa[2 * j + 1]) : "r"(x23));
                }
                // rowsum += P @ ones
                asm volatile(
                    "mma.sync.aligned.m16n8k16.row.col.f32.f16.f16.f32 "
                    "{%0,%1,%2,%3}, {%4,%5,%6,%7}, {%8,%9}, {%0,%1,%2,%3};"
                    : "+f"(rsacc[0]), "+f"(rsacc[1]), "+f"(rsacc[2]), "+f"(rsacc[3])
                    : "r"(pa[0]), "r"(pa[1]), "r"(pa[2]), "r"(pa[3]),
                      "r"(ONES), "r"(ONES));
                // O += P @ V
                uint32_t bfr[4][4];
                #pragma unroll
                for (int t = 0; t < 4; t++) {
                    uint32_t sbb = sV + ((kk * 16 + brow) * PB + t * 16 + bcol8) * 2;
                    asm volatile(
                        "ldmatrix.sync.aligned.m8n8.x4.trans.shared.b16 {%0,%1,%2,%3}, [%4];"
                        : "=r"(bfr[t][0]), "=r"(bfr[t][1]), "=r"(bfr[t][2]), "=r"(bfr[t][3])
                        : "r"(sbb));
                }
                #pragma unroll
                for (int ni = 0; ni < 8; ni++) {
                    uint32_t b0 = bfr[ni >> 1][(ni & 1) * 2];
                    uint32_t b1 = bfr[ni >> 1][(ni & 1) * 2 + 1];
                    asm volatile(
                        "mma.sync.aligned.m16n8k16.row.col.f32.f16.f16.f32 "
                        "{%0,%1,%2,%3}, {%4,%5,%6,%7}, {%8,%9}, {%0,%1,%2,%3};"
                        : "+f"(oacc[ni][0]), "+f"(oacc[ni][1]),
                          "+f"(oacc[ni][2]), "+f"(oacc[ni][3])
                        : "r"(pa[0]), "r"(pa[1]), "r"(pa[2]), "r"(pa[3]),
                          "r"(b0), "r"(b1));
                }
            }
        }
        __syncthreads();
        buf ^= 1;
    }

    // epilogue: subtract OOB rowsum overcount (exactly 320-307=13), store
    #pragma unroll
    for (int u = 0; u < 2; u++) {
        int gr = n0 + qrow_frag + u * 8;
        if (gr >= N_) continue;
        float inv = 1.f / (rsacc[2 * u] - 13.0f);
        #pragma unroll
        for (int ni = 0; ni < 8; ni++) {
            int dc = ni * 8 + 2 * l4;
            *(uint32_t*)(out + gbase + (size_t)gr * D_ + dc) =
                pack_f16x2(oacc[ni][2 * u] * inv, oacc[ni][2 * u + 1] * inv);
        }
    }
}

// ---------------- launch ----------------
extern "C" void kernel_launch(void* const* d_in, const int* in_sizes, int n_in,
                              void* d_out, int out_size)
{
    const float* query = (const float*)d_in[0];
    const float* key   = (const float*)d_in[1];
    const float* value = (const float*)d_in[2];
    const float* sem   = (const float*)d_in[3];
    const float* Wq    = (const float*)d_in[4];
    const float* bq    = (const float*)d_in[5];
    const float* Wk    = (const float*)d_in[6];
    const float* bk    = (const float*)d_in[7];
    const float* Wv    = (const float*)d_in[8];
    const float* bv    = (const float*)d_in[9];
    const float* Wo    = (const float*)d_in[10];
    const float* bo    = (const float*)d_in[11];
    float* out = (float*)d_out;

    __half *mask_p, *qh_p, *kh_p, *vh_p, *oh_p, *wt_p;
    cudaGetSymbolAddress((void**)&mask_p, g_maskh);
    cudaGetSymbolAddress((void**)&qh_p,   g_qh);
    cudaGetSymbolAddress((void**)&kh_p,   g_kh);
    cudaGetSymbolAddress((void**)&vh_p,   g_vh);
    cudaGetSymbolAddress((void**)&oh_p,   g_oh);
    cudaGetSymbolAddress((void**)&wt_p,   g_wt);

    static bool attr_set = false;
    if (!attr_set) {
        cudaFuncSetAttribute(attn_mma_kernel,
                             cudaFuncAttributeMaxDynamicSharedMemorySize, ATTN_SMEM);
        cudaFuncSetAttribute(gemm_bias_f16_kernel<false, true>,
                             cudaFuncAttributeMaxDynamicSharedMemorySize, GEMM_SMEM);
        cudaFuncSetAttribute(gemm_bias_f16_kernel<true, false>,
                             cudaFuncAttributeMaxDynamicSharedMemorySize, GEMM_SMEM);
        attr_set = true;
    }

    mask_softmax_kernel<<<N_, 256>>>(sem, mask_p);

    dim3 tg(D_ / 32, D_ / 32, 4);
    transpose_w_kernel<<<tg, dim3(32, 8)>>>(Wq, Wk, Wv, Wo, wt_p);

    dim3 g3(D_ / 128, (M_TOT + 127) / 128, 3);
    gemm_bias_f16_kernel<false, true><<<g3, 256, GEMM_SMEM>>>(
        query, key, value, wt_p, bq, bk, bv, qh_p, kh_p, vh_p, M_TOT);

    dim3 ga((N_ + 127) / 128, B_ * T_ * H_);
    attn_mma_kernel<<<ga, 256, ATTN_SMEM>>>(qh_p, kh_p, vh_p, mask_p, oh_p);

    dim3 g1(D_ / 128, (M_TOT + 127) / 128, 1);
    gemm_bias_f16_kernel<true, false><<<g1, 256, GEMM_SMEM>>>(
        oh_p, oh_p, oh_p, wt_p + 3 * (size_t)D_ * D_, bo, bo, bo,
        out, out, out, M_TOT);
}

// round 17
// speedup vs baseline: 1.4763x; 1.0128x over previous
#include <cuda_runtime.h>
#include <cuda_fp16.h>
#include <math.h>
#include <cstdint>

#define B_   8
#define T_   12
#define N_   307
#define D_   512
#define H_   8
#define HD_  64
#define M_TOT (B_*T_*N_)   // 29472
#define MP   320           // padded mask row pitch (halves)

// ---------------- device scratch (allocation-free rule) ----------------
__device__ __half g_maskh[N_*MP];          // fp16 mask, premul by 0.125*log2e
__device__ __half g_qh[M_TOT*D_];
__device__ __half g_kh[M_TOT*D_];
__device__ __half g_vh[M_TOT*D_];
__device__ __half g_oh[M_TOT*D_];
__device__ __half g_wt[4*D_*D_];           // transposed fp16 weights [N][K]

__device__ __forceinline__ uint32_t pack_f16x2(float lo, float hi) {
    uint32_t r;
    asm("cvt.rn.f16x2.f32 %0, %1, %2;" : "=r"(r) : "f"(hi), "f"(lo));
    return r;
}

// ---------------- mask = row-softmax * (0.125*log2e) -> fp16 -----------
__global__ void mask_softmax_kernel(const float* __restrict__ sem,
                                    __half* __restrict__ mask)
{
    int row = blockIdx.x;
    int tid = threadIdx.x;
    __shared__ float red[256];
    const float* x = sem + (size_t)row * N_;
    float v0 = (tid       < N_) ? x[tid]       : -INFINITY;
    float v1 = (tid + 256 < N_) ? x[tid + 256] : -INFINITY;
    red[tid] = fmaxf(v0, v1);
    __syncthreads();
    for (int s = 128; s > 0; s >>= 1) {
        if (tid < s) red[tid] = fmaxf(red[tid], red[tid + s]);
        __syncthreads();
    }
    float rowmax = red[0];
    __syncthreads();
    float e0 = (tid       < N_) ? __expf(v0 - rowmax) : 0.f;
    float e1 = (tid + 256 < N_) ? __expf(v1 - rowmax) : 0.f;
    red[tid] = e0 + e1;
    __syncthreads();
    for (int s = 128; s > 0; s >>= 1) {
        if (tid < s) red[tid] += red[tid + s];
        __syncthreads();
    }
    float inv = 0.180336880f / red[0];   // 0.125 * log2(e) / sum
    if (tid       < N_) mask[(size_t)row * MP + tid]       = __float2half(e0 * inv);
    if (tid + 256 < N_) mask[(size_t)row * MP + tid + 256] = __float2half(e1 * inv);
    if (tid == 0)
        for (int c = N_; c < MP; c++) mask[(size_t)row * MP + c] = __float2half(0.f);
}

// ---------------- W -> W^T (fp16), 4 matrices ----------------
__global__ void transpose_w_kernel(const float* __restrict__ w0,
                                   const float* __restrict__ w1,
                                   const float* __restrict__ w2,
                                   const float* __restrict__ w3,
                                   __half* __restrict__ wt)
{
    __shared__ float t[32][33];
    int z  = blockIdx.z;
    const float* src = (z == 0) ? w0 : (z == 1) ? w1 : (z == 2) ? w2 : w3;
    __half* dst = wt + (size_t)z * D_ * D_;
    int tx = threadIdx.x, ty = threadIdx.y;
    int bx = blockIdx.x * 32, by = blockIdx.y * 32;
    #pragma unroll
    for (int i = 0; i < 32; i += 8)
        t[ty + i][tx] = src[(size_t)(by + ty + i) * D_ + bx + tx];
    __syncthreads();
    #pragma unroll
    for (int i = 0; i < 32; i += 8)
        dst[(size_t)(bx + ty + i) * D_ + by + tx] = __float2half(t[tx][ty + i]);
}

// ---------------- fp16 mma GEMM (m16n8k16), frozen ---------------------
#define GP 72
#define TILE_H (128 * GP)
#define GEMM_SMEM (4 * TILE_H * 2)        // 73728 B

template<bool F16_IN, bool F16_OUT>
__global__ __launch_bounds__(256, 2)
void gemm_bias_f16_kernel(const void* __restrict__ A0, const void* __restrict__ A1,
                          const void* __restrict__ A2, const __half* __restrict__ WtB,
                          const float* __restrict__ b0p, const float* __restrict__ b1p,
                          const float* __restrict__ b2p,
                          void* __restrict__ C0, void* __restrict__ C1,
                          void* __restrict__ C2, int M)
{
    extern __shared__ __half gsh[];
    int z = blockIdx.z;
    const void* Av     = (z == 0) ? A0 : (z == 1) ? A1 : A2;
    const __half* Wt   = WtB + (size_t)z * D_ * D_;
    const float* bias  = (z == 0) ? b0p : (z == 1) ? b1p : b2p;
    void* Cv           = (z == 0) ? C0 : (z == 1) ? C1 : C2;

    int tid  = threadIdx.x;
    int lane = tid & 31;
    int wid  = tid >> 5;
    int warp_m = wid & 1;
    int warp_n = wid >> 1;
    int m0 = blockIdx.y * 128;
    int n0 = blockIdx.x * 128;

    float acc[4][4][4];
    #pragma unroll
    for (int mi = 0; mi < 4; mi++)
        #pragma unroll
        for (int ni = 0; ni < 4; ni++)
            #pragma unroll
            for (int r = 0; r < 4; r++) acc[mi][ni][r] = 0.f;

    float4 stA[4][2];

    auto ldg_A = [&](int k0) {
        const float* A = (const float*)Av;
        #pragma unroll
        for (int r = 0; r < 4; r++) {
            int e   = tid + r * 256;
            int row = e >> 3;
            int seg = e & 7;
            int gm = m0 + row;
            if (gm < M) {
                const float* src = A + (size_t)gm * D_ + k0 + seg * 8;
                stA[r][0] = *(const float4*)(src);
                stA[r][1] = *(const float4*)(src + 4);
            } else {
                stA[r][0] = make_float4(0.f, 0.f, 0.f, 0.f);
                stA[r][1] = make_float4(0.f, 0.f, 0.f, 0.f);
            }
        }
    };
    auto sts_A = [&](int b) {
        __half* Ab = gsh + b * 2 * TILE_H;
        #pragma unroll
        for (int r = 0; r < 4; r++) {
            int e   = tid + r * 256;
            int row = e >> 3;
            int seg = e & 7;
            uint4 p;
            p.x = pack_f16x2(stA[r][0].x, stA[r][0].y);
            p.y = pack_f16x2(stA[r][0].z, stA[r][0].w);
            p.z = pack_f16x2(stA[r][1].x, stA[r][1].y);
            p.w = pack_f16x2(stA[r][1].z, stA[r][1].w);
            *(uint4*)(Ab + row * GP + seg * 8) = p;
        }
    };
    auto cpa_A = [&](int b, int k0) {
        const __half* A = (const __half*)Av;
        __half* Ab = gsh + b * 2 * TILE_H;
        #pragma unroll
        for (int r = 0; r < 4; r++) {
            int e   = tid + r * 256;
            int row = e >> 3;
            int seg = e & 7;
            int gm = m0 + row;
            const __half* src = A + (size_t)(gm < M ? gm : 0) * D_ + k0 + seg * 8;
            int sz = (gm < M) ? 16 : 0;
            uint32_t dst = (uint32_t)__cvta_generic_to_shared(Ab + row * GP + seg * 8);
            asm volatile("cp.async.ca.shared.global [%0], [%1], 16, %2;"
                         :: "r"(dst), "l"(src), "r"(sz));
        }
    };
    auto cpa_W = [&](int b, int k0) {
        __half* Wb = gsh + b * 2 * TILE_H + TILE_H;
        #pragma unroll
        for (int r = 0; r < 4; r++) {
            int e   = tid + r * 256;
            int row = e >> 3;
            int seg = e & 7;
            uint32_t dst = (uint32_t)__cvta_generic_to_shared(Wb + row * GP + seg * 8);
            const __half* src = Wt + (size_t)(n0 + row) * D_ + k0 + seg * 8;
            asm volatile("cp.async.ca.shared.global [%0], [%1], 16;"
                         :: "r"(dst), "l"(src));
        }
        asm volatile("cp.async.commit_group;");
    };

    if (F16_IN) { cpa_A(0, 0); cpa_W(0, 0); }
    else        { ldg_A(0); cpa_W(0, 0); sts_A(0); }
    asm volatile("cp.async.wait_group 0;");
    __syncthreads();

    int arow_sub = lane & 15;
    int acol8    = (lane >> 4) * 8;
    int brow_sub = (lane & 7) + ((lane >> 3) & 1) * 8;
    int bcol8    = (lane >> 4) * 8;

    int buf = 0;
    for (int k0 = 0; k0 < D_; k0 += 64) {
        bool last = (k0 == D_ - 64);
        if (!last) {
            if (F16_IN) { cpa_A(buf ^ 1, k0 + 64); cpa_W(buf ^ 1, k0 + 64); }
            else        { ldg_A(k0 + 64); cpa_W(buf ^ 1, k0 + 64); }
        }

        __half* Ab = gsh + buf * 2 * TILE_H;
        __half* Wb = Ab + TILE_H;
        #pragma unroll
        for (int kk = 0; kk < 4; kk++) {
            uint32_t a[4][4];
            #pragma unroll
            for (int mi = 0; mi < 4; mi++) {
                uint32_t sa = (uint32_t)__cvta_generic_to_shared(
                    Ab + (warp_m * 64 + mi * 16 + arow_sub) * GP + kk * 16 + acol8);
                asm volatile(
                    "ldmatrix.sync.aligned.m8n8.x4.shared.b16 {%0,%1,%2,%3}, [%4];"
                    : "=r"(a[mi][0]), "=r"(a[mi][1]), "=r"(a[mi][2]), "=r"(a[mi][3])
                    : "r"(sa));
            }
            uint32_t bfr[2][4];
            #pragma unroll
            for (int t = 0; t < 2; t++) {
                uint32_t sbb = (uint32_t)__cvta_generic_to_shared(
                    Wb + (warp_n * 32 + t * 16 + brow_sub) * GP + kk * 16 + bcol8);
                asm volatile(
                    "ldmatrix.sync.aligned.m8n8.x4.shared.b16 {%0,%1,%2,%3}, [%4];"
                    : "=r"(bfr[t][0]), "=r"(bfr[t][1]), "=r"(bfr[t][2]), "=r"(bfr[t][3])
                    : "r"(sbb));
            }
            #pragma unroll
            for (int ni = 0; ni < 4; ni++) {
                uint32_t b0 = bfr[ni >> 1][ni & 1];
                uint32_t b1 = bfr[ni >> 1][(ni & 1) + 2];
                #pragma unroll
                for (int mi = 0; mi < 4; mi++) {
                    asm volatile(
                        "mma.sync.aligned.m16n8k16.row.col.f32.f16.f16.f32 "
                        "{%0,%1,%2,%3}, {%4,%5,%6,%7}, {%8,%9}, {%0,%1,%2,%3};"
                        : "+f"(acc[mi][ni][0]), "+f"(acc[mi][ni][1]),
                          "+f"(acc[mi][ni][2]), "+f"(acc[mi][ni][3])
                        : "r"(a[mi][0]), "r"(a[mi][1]), "r"(a[mi][2]), "r"(a[mi][3]),
                          "r"(b0), "r"(b1));
                }
            }
        }
        if (!last) {
            if (!F16_IN) sts_A(buf ^ 1);
            asm volatile("cp.async.wait_group 0;");
            __syncthreads();
            buf ^= 1;
        }
    }

    int crow = m0 + warp_m * 64 + (lane >> 2);
    int ccol0 = n0 + warp_n * 32 + 2 * (lane & 3);
    #pragma unroll
    for (int mi = 0; mi < 4; mi++) {
        int r0 = crow + mi * 16;
        #pragma unroll
        for (int ni = 0; ni < 4; ni++) {
            int cc = ccol0 + ni * 8;
            float bb0 = bias[cc], bb1 = bias[cc + 1];
            if (F16_OUT) {
                __half* C = (__half*)Cv;
                if (r0 < M)
                    *(uint32_t*)(C + (size_t)r0 * D_ + cc) =
                        pack_f16x2(acc[mi][ni][0] + bb0, acc[mi][ni][1] + bb1);
                if (r0 + 8 < M)
                    *(uint32_t*)(C + (size_t)(r0 + 8) * D_ + cc) =
                        pack_f16x2(acc[mi][ni][2] + bb0, acc[mi][ni][3] + bb1);
            } else {
                float* C = (float*)Cv;
                if (r0 < M) {
                    float2 o = make_float2(acc[mi][ni][0] + bb0, acc[mi][ni][1] + bb1);
                    *(float2*)(C + (size_t)r0 * D_ + cc) = o;
                }
                if (r0 + 8 < M) {
                    float2 o = make_float2(acc[mi][ni][2] + bb0, acc[mi][ni][3] + bb1);
                    *(float2*)(C + (size_t)(r0 + 8) * D_ + cc) = o;
                }
            }
        }
    }
}

// ---------------- fp16 flash attention: single barrier per KV tile -----
// load for tile it+1 is issued AFTER the top barrier of tile it, into the
// buffer released by tile it-1 -> the one barrier provides both cp.async
// visibility and overwrite protection. Prefetch distance unchanged.
#define PB 72
#define SM_Q  0
#define SM_K  (128 * PB)                     // [2][64*PB]
#define SM_V  (SM_K + 2 * 64 * PB)           // [2][64*PB]
#define SM_M  (SM_V + 2 * 64 * PB)           // [2][128*PB]
#define ATTN_SMEM ((SM_M + 2 * 128 * PB) * 2)   // 92160 B

__global__ __launch_bounds__(256, 2)
void attn_mma_kernel(const __half* __restrict__ q,
                     const __half* __restrict__ k,
                     const __half* __restrict__ v,
                     const __half* __restrict__ maskh,
                     __half* __restrict__ out)
{
    extern __shared__ char smc[];
    uint32_t sb = (uint32_t)__cvta_generic_to_shared(smc);
    const uint32_t sQ = sb + SM_Q * 2;
    const uint32_t sK0 = sb + SM_K * 2;
    const uint32_t sV0 = sb + SM_V * 2;
    const uint32_t sM0 = sb + SM_M * 2;

    int tid  = threadIdx.x;
    int lane = tid & 31;
    int wid  = tid >> 5;
    int bth  = blockIdx.y;
    int bt   = bth / H_;
    int h    = bth % H_;
    int n0   = blockIdx.x * 128;
    size_t gbase = (size_t)bt * N_ * D_ + (size_t)h * HD_;
    bool wactive = (n0 + wid * 16) < N_;   // warp has >=1 valid q row

    // Q tile via cp.async (rides commit group of load_kvm(0,0))
    #pragma unroll
    for (int r = 0; r < 4; r++) {
        int e    = tid + r * 256;
        int row  = e >> 3;
        int cseg = e & 7;
        int gn = n0 + row;
        const __half* src = q + gbase + (size_t)(gn < N_ ? gn : 0) * D_ + cseg * 8;
        uint32_t dst = sQ + (row * PB + cseg * 8) * 2;
        int sz = (gn < N_) ? 16 : 0;
        asm volatile("cp.async.ca.shared.global [%0], [%1], 16, %2;"
                     :: "r"(dst), "l"(src), "r"(sz));
    }
    // K/V + mask tiles, one commit group
    auto load_kvm = [&](int m0, int buf) {
        uint32_t kdst0 = sK0 + buf * 64 * PB * 2;
        uint32_t vdst0 = sV0 + buf * 64 * PB * 2;
        uint32_t mdst0 = sM0 + buf * 128 * PB * 2;
        #pragma unroll
        for (int r = 0; r < 2; r++) {
            int e    = tid + r * 256;
            int row  = e >> 3;
            int cseg = e & 7;
            int gm = m0 + row;
            size_t goff = gbase + (size_t)(gm < N_ ? gm : 0) * D_ + cseg * 8;
            int sz = (gm < N_) ? 16 : 0;
            uint32_t kd = kdst0 + (row * PB + cseg * 8) * 2;
            uint32_t vd = vdst0 + (row * PB + cseg * 8) * 2;
            asm volatile("cp.async.ca.shared.global [%0], [%1], 16, %2;"
                         :: "r"(kd), "l"(k + goff), "r"(sz));
            asm volatile("cp.async.ca.shared.global [%0], [%1], 16, %2;"
                         :: "r"(vd), "l"(v + goff), "r"(sz));
        }
        #pragma unroll
        for (int r = 0; r < 4; r++) {
            int e    = tid + r * 256;
            int row  = e >> 3;
            int cseg = e & 7;
            int gr = n0 + row;
            const __half* src = maskh + (size_t)(gr < N_ ? gr : 0) * MP + m0 + cseg * 8;
            uint32_t md = mdst0 + (row * PB + cseg * 8) * 2;
            asm volatile("cp.async.ca.shared.global [%0], [%1], 16;"
                         :: "r"(md), "l"(src));
        }
        asm volatile("cp.async.commit_group;");
    };

    load_kvm(0, 0);

    float oacc[8][4];
    #pragma unroll
    for (int ni = 0; ni < 8; ni++)
        #pragma unroll
        for (int r = 0; r < 4; r++) oacc[ni][r] = 0.f;
    float rsacc[4] = {0.f, 0.f, 0.f, 0.f};
    const uint32_t ONES = 0x3C003C00u;   // (1.0h, 1.0h)

    int qrow_frag = wid * 16 + (lane >> 2);   // row r (and r+8)
    int arow  = wid * 16 + (lane & 15);
    int acol8 = (lane >> 4) * 8;
    int brow  = (lane & 7) + ((lane >> 3) & 1) * 8;
    int bcol8 = (lane >> 4) * 8;
    int l4 = lane & 3;

    int buf = 0;
    for (int it = 0; it < 5; it++) {
        // one barrier: data for tile `it` visible AND previous compute done
        asm volatile("cp.async.wait_group 0;" ::: "memory");
        __syncthreads();
        if (it < 4) load_kvm((it + 1) * 64, buf ^ 1);   // overlaps this tile's compute

        if (wactive) {
            int m0 = it * 64;
            uint32_t sK = sK0 + buf * 64 * PB * 2;
            uint32_t sV = sV0 + buf * 64 * PB * 2;
            uint32_t sM = sM0 + buf * 128 * PB * 2;

            // ---- S = Q @ K^T ----
            float sacc[8][4];
            #pragma unroll
            for (int ni = 0; ni < 8; ni++)
                #pragma unroll
                for (int r = 0; r < 4; r++) sacc[ni][r] = 0.f;
            #pragma unroll
            for (int kk = 0; kk < 4; kk++) {
                uint32_t a[4];
                uint32_t sa = sQ + (arow * PB + kk * 16 + acol8) * 2;
                asm volatile(
                    "ldmatrix.sync.aligned.m8n8.x4.shared.b16 {%0,%1,%2,%3}, [%4];"
                    : "=r"(a[0]), "=r"(a[1]), "=r"(a[2]), "=r"(a[3]) : "r"(sa));
                uint32_t bfr[4][4];
                #pragma unroll
                for (int t = 0; t < 4; t++) {
                    uint32_t sbb = sK + ((t * 16 + brow) * PB + kk * 16 + bcol8) * 2;
                    asm volatile(
                        "ldmatrix.sync.aligned.m8n8.x4.shared.b16 {%0,%1,%2,%3}, [%4];"
                        : "=r"(bfr[t][0]), "=r"(bfr[t][1]), "=r"(bfr[t][2]), "=r"(bfr[t][3])
                        : "r"(sbb));
                }
                #pragma unroll
                for (int ni = 0; ni < 8; ni++) {
                    uint32_t b0 = bfr[ni >> 1][ni & 1];
                    uint32_t b1 = bfr[ni >> 1][(ni & 1) + 2];
                    asm volatile(
                        "mma.sync.aligned.m16n8k16.row.col.f32.f16.f16.f32 "
                        "{%0,%1,%2,%3}, {%4,%5,%6,%7}, {%8,%9}, {%0,%1,%2,%3};"
                        : "+f"(sacc[ni][0]), "+f"(sacc[ni][1]),
                          "+f"(sacc[ni][2]), "+f"(sacc[ni][3])
                        : "r"(a[0]), "r"(a[1]), "r"(a[2]), "r"(a[3]),
                          "r"(b0), "r"(b1));
                }
            }

            // ---- softmax in f16x2 + P@V + rowsum, per k-chunk ----
            #pragma unroll
            for (int kk = 0; kk < 4; kk++) {
                uint32_t pa[4];
                #pragma unroll
                for (int j = 0; j < 2; j++) {
                    int ni = 2 * kk + j;
                    int c  = ni * 8 + 2 * l4;
                    uint32_t mh0, mh1;
                    asm volatile("ld.shared.b32 %0, [%1];"
                                 : "=r"(mh0) : "r"(sM + (qrow_frag * PB + c) * 2));
                    asm volatile("ld.shared.b32 %0, [%1];"
                                 : "=r"(mh1) : "r"(sM + ((qrow_frag + 8) * PB + c) * 2));
                    uint32_t s01 = pack_f16x2(sacc[ni][0], sacc[ni][1]);
                    uint32_t s23 = pack_f16x2(sacc[ni][2], sacc[ni][3]);
                    uint32_t x01, x23;
                    asm("mul.rn.f16x2 %0, %1, %2;" : "=r"(x01) : "r"(s01), "r"(mh0));
                    asm("mul.rn.f16x2 %0, %1, %2;" : "=r"(x23) : "r"(s23), "r"(mh1));
                    asm("ex2.approx.f16x2 %0, %1;" : "=r"(pa[2 * j])     : "r"(x01));
                    asm("ex2.approx.f16x2 %0, %1;" : "=r"(pa[2 * j + 1]) : "r"(x23));
                }
                // rowsum += P @ ones
                asm volatile(
                    "mma.sync.aligned.m16n8k16.row.col.f32.f16.f16.f32 "
                    "{%0,%1,%2,%3}, {%4,%5,%6,%7}, {%8,%9}, {%0,%1,%2,%3};"
                    : "+f"(rsacc[0]), "+f"(rsacc[1]), "+f"(rsacc[2]), "+f"(rsacc[3])
                    : "r"(pa[0]), "r"(pa[1]), "r"(pa[2]), "r"(pa[3]),
                      "r"(ONES), "r"(ONES));
                // O += P @ V
                uint32_t bfr[4][4];
                #pragma unroll
                for (int t = 0; t < 4; t++) {
                    uint32_t sbb = sV + ((kk * 16 + brow) * PB + t * 16 + bcol8) * 2;
                    asm volatile(
                        "ldmatrix.sync.aligned.m8n8.x4.trans.shared.b16 {%0,%1,%2,%3}, [%4];"
                        : "=r"(bfr[t][0]), "=r"(bfr[t][1]), "=r"(bfr[t][2]), "=r"(bfr[t][3])
                        : "r"(sbb));
                }
                #pragma unroll
                for (int ni = 0; ni < 8; ni++) {
                    uint32_t b0 = bfr[ni >> 1][(ni & 1) * 2];
                    uint32_t b1 = bfr[ni >> 1][(ni & 1) * 2 + 1];
                    asm volatile(
                        "mma.sync.aligned.m16n8k16.row.col.f32.f16.f16.f32 "
                        "{%0,%1,%2,%3}, {%4,%5,%6,%7}, {%8,%9}, {%0,%1,%2,%3};"
                        : "+f"(oacc[ni][0]), "+f"(oacc[ni][1]),
                          "+f"(oacc[ni][2]), "+f"(oacc[ni][3])
                        : "r"(pa[0]), "r"(pa[1]), "r"(pa[2]), "r"(pa[3]),
                          "r"(b0), "r"(b1));
                }
            }
        }
        buf ^= 1;
    }

    // epilogue: subtract OOB rowsum overcount (exactly 320-307=13), store
    #pragma unroll
    for (int u = 0; u < 2; u++) {
        int gr = n0 + qrow_frag + u * 8;
        if (gr >= N_) continue;
        float inv = 1.f / (rsacc[2 * u] - 13.0f);
        #pragma unroll
        for (int ni = 0; ni < 8; ni++) {
            int dc = ni * 8 + 2 * l4;
            *(uint32_t*)(out + gbase + (size_t)gr * D_ + dc) =
                pack_f16x2(oacc[ni][2 * u] * inv, oacc[ni][2 * u + 1] * inv);
        }
    }
}

// ---------------- launch ----------------
extern "C" void kernel_launch(void* const* d_in, const int* in_sizes, int n_in,
                              void* d_out, int out_size)
{
    const float* query = (const float*)d_in[0];
    const float* key   = (const float*)d_in[1];
    const float* value = (const float*)d_in[2];
    const float* sem   = (const float*)d_in[3];
    const float* Wq    = (const float*)d_in[4];
    const float* bq    = (const float*)d_in[5];
    const float* Wk    = (const float*)d_in[6];
    const float* bk    = (const float*)d_in[7];
    const float* Wv    = (const float*)d_in[8];
    const float* bv    = (const float*)d_in[9];
    const float* Wo    = (const float*)d_in[10];
    const float* bo    = (const float*)d_in[11];
    float* out = (float*)d_out;

    __half *mask_p, *qh_p, *kh_p, *vh_p, *oh_p, *wt_p;
    cudaGetSymbolAddress((void**)&mask_p, g_maskh);
    cudaGetSymbolAddress((void**)&qh_p,   g_qh);
    cudaGetSymbolAddress((void**)&kh_p,   g_kh);
    cudaGetSymbolAddress((void**)&vh_p,   g_vh);
    cudaGetSymbolAddress((void**)&oh_p,   g_oh);
    cudaGetSymbolAddress((void**)&wt_p,   g_wt);

    static bool attr_set = false;
    if (!attr_set) {
        cudaFuncSetAttribute(attn_mma_kernel,
                             cudaFuncAttributeMaxDynamicSharedMemorySize, ATTN_SMEM);
        cudaFuncSetAttribute(gemm_bias_f16_kernel<false, true>,
                             cudaFuncAttributeMaxDynamicSharedMemorySize, GEMM_SMEM);
        cudaFuncSetAttribute(gemm_bias_f16_kernel<true, false>,
                             cudaFuncAttributeMaxDynamicSharedMemorySize, GEMM_SMEM);
        attr_set = true;
    }

    mask_softmax_kernel<<<N_, 256>>>(sem, mask_p);

    dim3 tg(D_ / 32, D_ / 32, 4);
    transpose_w_kernel<<<tg, dim3(32, 8)>>>(Wq, Wk, Wv, Wo, wt_p);

    dim3 g3(D_ / 128, (M_TOT + 127) / 128, 3);
    gemm_bias_f16_kernel<false, true><<<g3, 256, GEMM_SMEM>>>(
        query, key, value, wt_p, bq, bk, bv, qh_p, kh_p, vh_p, M_TOT);

    dim3 ga((N_ + 127) / 128, B_ * T_ * H_);
    attn_mma_kernel<<<ga, 256, ATTN_SMEM>>>(qh_p, kh_p, vh_p, mask_p, oh_p);

    dim3 g1(D_ / 128, (M_TOT + 127) / 128, 1);
    gemm_bias_f16_kernel<true, false><<<g1, 256, GEMM_SMEM>>>(
        oh_p, oh_p, oh_p, wt_p + 3 * (size_t)D_ * D_, bo, bo, bo,
        out, out, out, M_TOT);
}